// round 1
// baseline (speedup 1.0000x reference)
#include <cuda_runtime.h>
#include <cstdint>

#define NBOX      5000
#define NCLS      81
#define MAXI      100
#define CANDMAX   1024
#define MIN_CONF  0.7f
#define NMS_THR   0.3f

// Persistent device scratch (rewritten fully every launch -> deterministic).
__device__ float g_box[NBOX * 4];
__device__ float g_score[NBOX];
__device__ int   g_cls[NBOX];    // 0 if invalid, else class id (>=1)
__device__ int   g_kept[NBOX];

// ---------------------------------------------------------------------------
// Kernel A: one warp per ROI. Argmax over 81 classes (first-max tie-break),
// class-specific delta refine, clip to window. Also clears kept flags.
// ---------------------------------------------------------------------------
__global__ void k_refine(const float* __restrict__ rois,
                         const float* __restrict__ probs,
                         const float* __restrict__ deltas,
                         const float* __restrict__ window)
{
    int warpId = (blockIdx.x * blockDim.x + threadIdx.x) >> 5;
    int lane   = threadIdx.x & 31;
    if (warpId >= NBOX) return;

    const float* p = probs + warpId * NCLS;
    float bp = -1.0f;
    int   bi = 0;
    // lane's indices are increasing; strict > keeps the earliest maximum.
    for (int c = lane; c < NCLS; c += 32) {
        float v = p[c];
        if (v > bp) { bp = v; bi = c; }
    }
    // cross-lane reduce: higher prob wins; tie -> lower index (first occurrence)
    for (int off = 16; off; off >>= 1) {
        float op = __shfl_down_sync(0xffffffffu, bp, off);
        int   oi = __shfl_down_sync(0xffffffffu, bi, off);
        if (op > bp || (op == bp && oi < bi)) { bp = op; bi = oi; }
    }

    if (lane == 0) {
        float y1r = rois[warpId * 4 + 0];
        float x1r = rois[warpId * 4 + 1];
        float y2r = rois[warpId * 4 + 2];
        float x2r = rois[warpId * 4 + 3];
        float h  = y2r - y1r;
        float w  = x2r - x1r;
        float cy = y1r + 0.5f * h;
        float cx = x1r + 0.5f * w;

        const float* d = deltas + ((size_t)warpId * NCLS + bi) * 4;
        float dy = d[0] * 0.1f;
        float dx = d[1] * 0.1f;
        float dh = d[2] * 0.2f;
        float dw = d[3] * 0.2f;

        cy += dy * h;
        cx += dx * w;
        h  *= expf(dh);
        w  *= expf(dw);

        float y1 = cy - 0.5f * h;
        float x1 = cx - 0.5f * w;
        float y2 = y1 + h;
        float x2 = x1 + w;

        float wy1 = window[0], wx1 = window[1], wy2 = window[2], wx2 = window[3];
        y1 = fminf(fmaxf(y1, wy1), wy2);
        x1 = fminf(fmaxf(x1, wx1), wx2);
        y2 = fminf(fmaxf(y2, wy1), wy2);
        x2 = fminf(fmaxf(x2, wx1), wx2);

        g_box[warpId * 4 + 0] = y1;
        g_box[warpId * 4 + 1] = x1;
        g_box[warpId * 4 + 2] = y2;
        g_box[warpId * 4 + 3] = x2;
        g_score[warpId] = bp;
        g_cls[warpId]   = (bi > 0 && bp >= MIN_CONF) ? bi : 0;
        g_kept[warpId]  = 0;
    }
}

// ---------------------------------------------------------------------------
// Kernel B: one block per class (1..80). Gather candidates, sort by
// (score desc, idx asc), greedy NMS with per-class cap of MAXI.
// ---------------------------------------------------------------------------
__global__ void k_nms()
{
    const int c   = blockIdx.x + 1;
    const int tid = threadIdx.x;
    const int bd  = blockDim.x;

    __shared__ unsigned long long keys[CANDMAX];
    __shared__ float by1[CANDMAX], bx1[CANDMAX], by2[CANDMAX], bx2[CANDMAX];
    __shared__ float barea[CANDMAX];
    __shared__ int   sidx[CANDMAX];
    __shared__ unsigned char keptF[CANDMAX];
    __shared__ int cnt, suppFlag, keptCount;

    if (tid == 0) { cnt = 0; keptCount = 0; }
    __syncthreads();

    // Gather candidates of this class.
    for (int r = tid; r < NBOX; r += bd) {
        if (g_cls[r] == c) {
            int pos = atomicAdd(&cnt, 1);
            if (pos < CANDMAX) {
                unsigned int su = __float_as_uint(g_score[r]);  // score > 0
                keys[pos] = ((unsigned long long)su << 32) |
                            (unsigned int)(0xFFFFFFFFu - (unsigned int)r);
            }
        }
    }
    __syncthreads();

    int k = min(cnt, CANDMAX);
    if (k == 0) return;

    int m = 1;
    while (m < k) m <<= 1;
    if (m < 2) m = 2;

    for (int t = tid; t < m; t += bd)
        if (t >= k) keys[t] = 0ULL;
    __syncthreads();

    // Bitonic ascending sort of m keys.
    for (int kk = 2; kk <= m; kk <<= 1) {
        for (int j = kk >> 1; j > 0; j >>= 1) {
            for (int i = tid; i < m; i += bd) {
                int ixj = i ^ j;
                if (ixj > i) {
                    bool up = ((i & kk) == 0);
                    unsigned long long a = keys[i], b = keys[ixj];
                    if ((a > b) == up) { keys[i] = b; keys[ixj] = a; }
                }
            }
            __syncthreads();
        }
    }

    // Load boxes in descending-score rank order.
    for (int t = tid; t < k; t += bd) {
        unsigned long long key = keys[m - 1 - t];
        int r = (int)(0xFFFFFFFFu - (unsigned int)(key & 0xFFFFFFFFu));
        sidx[t] = r;
        float y1 = g_box[r * 4 + 0];
        float x1 = g_box[r * 4 + 1];
        float y2 = g_box[r * 4 + 2];
        float x2 = g_box[r * 4 + 3];
        by1[t] = y1; bx1[t] = x1; by2[t] = y2; bx2[t] = x2;
        barea[t] = fmaxf(y2 - y1, 0.0f) * fmaxf(x2 - x1, 0.0f);
        keptF[t] = 0;
    }
    __syncthreads();

    // Greedy sequential NMS; parallel suppression test per candidate.
    for (int i = 0; i < k; i++) {
        if (tid == 0) suppFlag = 0;
        __syncthreads();

        float iy1 = by1[i], ix1 = bx1[i], iy2 = by2[i], ix2 = bx2[i];
        float ia  = barea[i];
        int loc = 0;
        for (int j = tid; j < i; j += bd) {
            if (keptF[j]) {
                float yy1 = fmaxf(iy1, by1[j]);
                float xx1 = fmaxf(ix1, bx1[j]);
                float yy2 = fminf(iy2, by2[j]);
                float xx2 = fminf(ix2, bx2[j]);
                float inter = fmaxf(yy2 - yy1, 0.0f) * fmaxf(xx2 - xx1, 0.0f);
                float uni   = ia + barea[j] - inter;
                float iou   = (uni > 0.0f) ? inter / fmaxf(uni, 1e-12f) : 0.0f;
                if (iou > NMS_THR) loc = 1;
            }
        }
        if (loc) suppFlag = 1;
        __syncthreads();

        if (tid == 0) {
            if (!suppFlag && keptCount < MAXI) {
                keptF[i] = 1;
                keptCount++;
                g_kept[sidx[i]] = 1;
            }
        }
        __syncthreads();
    }
}

// ---------------------------------------------------------------------------
// Kernel C: global top-MAXI of kept boxes. Histogram on score picks a
// threshold bin so that <= ~100+eps candidates remain; bitonic-sort those.
// ---------------------------------------------------------------------------
__global__ void k_topk(float* __restrict__ out)
{
    const int tid = threadIdx.x;  // 1024 threads
    __shared__ int hist[1024];
    __shared__ unsigned long long cand[1024];
    __shared__ int ccnt, bstar;

    hist[tid] = 0;
    if (tid == 0) { ccnt = 0; bstar = 0; }
    __syncthreads();

    // Histogram of kept scores (scores in [MIN_CONF, 1)).
    for (int r = tid; r < NBOX; r += 1024) {
        if (g_kept[r]) {
            float s = g_score[r];
            int b = (int)((s - 0.7f) * (1024.0f / 0.3f));
            b = min(1023, max(0, b));
            atomicAdd(&hist[b], 1);
        }
    }
    __syncthreads();

    // Suffix sums: hist[t] = count of kept with bin >= t.
    for (int step = 1; step < 1024; step <<= 1) {
        int v = hist[tid] + ((tid + step < 1024) ? hist[tid + step] : 0);
        __syncthreads();
        hist[tid] = v;
        __syncthreads();
    }

    // Largest b with S(b) >= MAXI (unique boundary; else stays 0).
    if (hist[tid] >= MAXI && (tid == 1023 || hist[tid + 1] < MAXI)) bstar = tid;
    __syncthreads();
    int B = bstar;

    // Collect candidate keys above threshold bin.
    for (int r = tid; r < NBOX; r += 1024) {
        if (g_kept[r]) {
            float s = g_score[r];
            int b = (int)((s - 0.7f) * (1024.0f / 0.3f));
            b = min(1023, max(0, b));
            if (b >= B) {
                int pos = atomicAdd(&ccnt, 1);
                if (pos < 1024) {
                    unsigned int su = __float_as_uint(s);
                    cand[pos] = ((unsigned long long)su << 32) |
                                (unsigned int)(0xFFFFFFFFu - (unsigned int)r);
                }
            }
        }
    }
    __syncthreads();
    int k = min(ccnt, 1024);
    if (tid >= k) cand[tid] = 0ULL;
    __syncthreads();

    // Bitonic ascending sort of 1024 keys (one element per thread).
    for (int kk = 2; kk <= 1024; kk <<= 1) {
        for (int j = kk >> 1; j > 0; j >>= 1) {
            int ixj = tid ^ j;
            if (ixj > tid) {
                bool up = ((tid & kk) == 0);
                unsigned long long a = cand[tid], b = cand[ixj];
                if ((a > b) == up) { cand[tid] = b; cand[ixj] = a; }
            }
            __syncthreads();
        }
    }

    // Emit top-100 rows (descending); zero-fill missing.
    if (tid < MAXI) {
        unsigned long long key = cand[1023 - tid];
        if (key >> 32) {
            int r = (int)(0xFFFFFFFFu - (unsigned int)(key & 0xFFFFFFFFu));
            out[tid * 6 + 0] = g_box[r * 4 + 0];
            out[tid * 6 + 1] = g_box[r * 4 + 1];
            out[tid * 6 + 2] = g_box[r * 4 + 2];
            out[tid * 6 + 3] = g_box[r * 4 + 3];
            out[tid * 6 + 4] = (float)g_cls[r];
            out[tid * 6 + 5] = g_score[r];
        } else {
            #pragma unroll
            for (int q = 0; q < 6; q++) out[tid * 6 + q] = 0.0f;
        }
    }
}

extern "C" void kernel_launch(void* const* d_in, const int* in_sizes, int n_in,
                              void* d_out, int out_size)
{
    const float* rois   = (const float*)d_in[0];
    const float* probs  = (const float*)d_in[1];
    const float* deltas = (const float*)d_in[2];
    const float* window = (const float*)d_in[3];
    float* out = (float*)d_out;

    // A: 1 warp per ROI, 4 warps per block.
    int blocksA = (NBOX * 32 + 127) / 128;
    k_refine<<<blocksA, 128>>>(rois, probs, deltas, window);

    // B: one block per class 1..80.
    k_nms<<<NCLS - 1, 256>>>();

    // C: single block top-k + output.
    k_topk<<<1, 1024>>>(out);
}

// round 2
// speedup vs baseline: 1.1954x; 1.1954x over previous
#include <cuda_runtime.h>
#include <cstdint>

#define NBOX      5000
#define NCLS      81
#define MAXI      100
#define CLSMAX    128          // per-class candidate cap (E≈62, σ≈7.8 → 8.5σ margin)
#define KEPTMAX   8192         // >= 80 * 100
#define NBLK      10           // NMS blocks: 10 x 8 warps = 80 classes
#define MIN_CONF  0.7f
#define NMS_THR   0.3f

// Persistent scratch. Counters are zero at module load and re-zeroed at the
// end of every launch by the last NMS block -> deterministic replays.
__device__ float              g_box[NBOX * 4];
__device__ float              g_score[NBOX];
__device__ int                g_cls[NBOX];
__device__ unsigned long long g_clsKeys[NCLS * CLSMAX];
__device__ int                g_clsCnt[NCLS];
__device__ unsigned long long g_keptKeys[KEPTMAX];
__device__ int                g_nkept;
__device__ int                g_done;

// ---------------------------------------------------------------------------
// Kernel A: one warp per 2 ROIs. Argmax over 81 classes (first-max tie-break),
// class-specific delta refine, clip, and bucket valid boxes by class.
// ---------------------------------------------------------------------------
__global__ void k_refine(const float* __restrict__ rois,
                         const float* __restrict__ probs,
                         const float* __restrict__ deltas,
                         const float* __restrict__ window)
{
    int w    = (blockIdx.x * blockDim.x + threadIdx.x) >> 5;
    int lane = threadIdx.x & 31;
    if (w >= NBOX / 2) return;

    const int r0 = 2 * w;
    const float* p0 = probs + (size_t)r0 * NCLS;
    const float* p1 = p0 + NCLS;

    float bp0 = -1.0f, bp1 = -1.0f;
    int   bi0 = 0,     bi1 = 0;
    #pragma unroll
    for (int it = 0; it < 3; it++) {
        int c = lane + it * 32;
        if (c < NCLS) {
            float v0 = p0[c];
            float v1 = p1[c];
            if (v0 > bp0) { bp0 = v0; bi0 = c; }
            if (v1 > bp1) { bp1 = v1; bi1 = c; }
        }
    }
    // Butterfly reduce (commutative-associative: max prob, tie -> lower idx).
    #pragma unroll
    for (int off = 16; off; off >>= 1) {
        float op0 = __shfl_xor_sync(0xffffffffu, bp0, off);
        int   oi0 = __shfl_xor_sync(0xffffffffu, bi0, off);
        float op1 = __shfl_xor_sync(0xffffffffu, bp1, off);
        int   oi1 = __shfl_xor_sync(0xffffffffu, bi1, off);
        if (op0 > bp0 || (op0 == bp0 && oi0 < bi0)) { bp0 = op0; bi0 = oi0; }
        if (op1 > bp1 || (op1 == bp1 && oi1 < bi1)) { bp1 = op1; bi1 = oi1; }
    }

    if (lane < 2) {
        int   r  = r0 + lane;
        float bp = (lane == 0) ? bp0 : bp1;
        int   bi = (lane == 0) ? bi0 : bi1;

        float y1r = rois[r * 4 + 0];
        float x1r = rois[r * 4 + 1];
        float y2r = rois[r * 4 + 2];
        float x2r = rois[r * 4 + 3];
        float h  = y2r - y1r;
        float wd = x2r - x1r;
        float cy = y1r + 0.5f * h;
        float cx = x1r + 0.5f * wd;

        const float* d = deltas + ((size_t)r * NCLS + bi) * 4;
        cy += (d[0] * 0.1f) * h;
        cx += (d[1] * 0.1f) * wd;
        h  *= expf(d[2] * 0.2f);
        wd *= expf(d[3] * 0.2f);

        float y1 = cy - 0.5f * h;
        float x1 = cx - 0.5f * wd;
        float y2 = y1 + h;
        float x2 = x1 + wd;

        float wy1 = window[0], wx1 = window[1], wy2 = window[2], wx2 = window[3];
        y1 = fminf(fmaxf(y1, wy1), wy2);
        x1 = fminf(fmaxf(x1, wx1), wx2);
        y2 = fminf(fmaxf(y2, wy1), wy2);
        x2 = fminf(fmaxf(x2, wx1), wx2);

        g_box[r * 4 + 0] = y1;
        g_box[r * 4 + 1] = x1;
        g_box[r * 4 + 2] = y2;
        g_box[r * 4 + 3] = x2;
        g_score[r] = bp;

        int cls = (bi > 0 && bp >= MIN_CONF) ? bi : 0;
        g_cls[r] = cls;
        if (cls > 0) {
            unsigned long long key =
                ((unsigned long long)__float_as_uint(bp) << 32) |
                (unsigned int)(0xFFFFFFFFu - (unsigned int)r);
            int pos = atomicAdd(&g_clsCnt[cls], 1);
            if (pos < CLSMAX) g_clsKeys[cls * CLSMAX + pos] = key;
        }
    }
}

// ---------------------------------------------------------------------------
// Kernel B (fused): warp-per-class NMS; last block performs global top-100.
// ---------------------------------------------------------------------------
__global__ void __launch_bounds__(256) k_nms_topk(float* __restrict__ out)
{
    const int tid  = threadIdx.x;
    const int warp = tid >> 5;
    const int lane = tid & 31;

    __shared__ unsigned long long s_keys[8][CLSMAX];
    __shared__ float s_y1[8][CLSMAX], s_x1[8][CLSMAX];
    __shared__ float s_y2[8][CLSMAX], s_x2[8][CLSMAX], s_ar[8][CLSMAX];
    __shared__ int   s_last;

    const int c = blockIdx.x * 8 + warp + 1;      // classes 1..80
    int cnt = min(g_clsCnt[c], CLSMAX);

    if (cnt > 0) {
        // Gather keys.
        for (int t = lane; t < cnt; t += 32)
            s_keys[warp][t] = g_clsKeys[c * CLSMAX + t];

        int m = 2;
        while (m < cnt) m <<= 1;                  // <= 128
        for (int t = lane; t < m; t += 32)
            if (t >= cnt) s_keys[warp][t] = 0ULL;
        __syncwarp();

        // Warp bitonic ascending sort of m keys.
        for (int kk = 2; kk <= m; kk <<= 1) {
            for (int j = kk >> 1; j > 0; j >>= 1) {
                for (int i = lane; i < m; i += 32) {
                    int ixj = i ^ j;
                    if (ixj > i) {
                        bool up = ((i & kk) == 0);
                        unsigned long long a = s_keys[warp][i];
                        unsigned long long b = s_keys[warp][ixj];
                        if ((a > b) == up) { s_keys[warp][i] = b; s_keys[warp][ixj] = a; }
                    }
                }
                __syncwarp();
            }
        }

        // Boxes in descending (score, -idx) order.
        for (int t = lane; t < cnt; t += 32) {
            unsigned long long key = s_keys[warp][m - 1 - t];
            int r = (int)(0xFFFFFFFFu - (unsigned int)(key & 0xFFFFFFFFu));
            float y1 = g_box[r * 4 + 0];
            float x1 = g_box[r * 4 + 1];
            float y2 = g_box[r * 4 + 2];
            float x2 = g_box[r * 4 + 3];
            s_y1[warp][t] = y1; s_x1[warp][t] = x1;
            s_y2[warp][t] = y2; s_x2[warp][t] = x2;
            s_ar[warp][t] = fmaxf(y2 - y1, 0.0f) * fmaxf(x2 - x1, 0.0f);
        }
        __syncwarp();

        // Greedy NMS. Kept box #k lives in lane k%32, slot k/32.
        float ky1[4], kx1[4], ky2[4], kx2[4], ka[4];
        int nkept = 0;
        for (int i = 0; i < cnt; i++) {
            float iy1 = s_y1[warp][i], ix1 = s_x1[warp][i];
            float iy2 = s_y2[warp][i], ix2 = s_x2[warp][i];
            float ia  = s_ar[warp][i];

            bool over = false;
            #pragma unroll
            for (int s = 0; s < 4; s++) {
                if (s * 32 + lane < nkept) {
                    float yy1 = fmaxf(iy1, ky1[s]);
                    float xx1 = fmaxf(ix1, kx1[s]);
                    float yy2 = fminf(iy2, ky2[s]);
                    float xx2 = fminf(ix2, kx2[s]);
                    float inter = fmaxf(yy2 - yy1, 0.0f) * fmaxf(xx2 - xx1, 0.0f);
                    float uni   = ia + ka[s] - inter;
                    // iou > THR  <=>  uni>0 && inter > THR*max(uni,1e-12)
                    if (uni > 0.0f && inter > NMS_THR * fmaxf(uni, 1e-12f)) over = true;
                }
            }
            unsigned bal = __ballot_sync(0xffffffffu, over);
            if (bal == 0u && nkept < MAXI) {
                if (lane == (nkept & 31)) {
                    int s = nkept >> 5;
                    ky1[s] = iy1; kx1[s] = ix1; ky2[s] = iy2; kx2[s] = ix2; ka[s] = ia;
                }
                if (lane == 0) {
                    int pos = atomicAdd(&g_nkept, 1);
                    g_keptKeys[pos] = s_keys[warp][m - 1 - i];
                }
                nkept++;
            }
        }
    }

    // ---- last-block handoff ----
    __syncthreads();
    if (tid == 0) {
        __threadfence();
        int prev = atomicAdd(&g_done, 1);
        s_last = (prev == NBLK - 1);
    }
    __syncthreads();
    if (!s_last) return;

    // ---------------- global top-100 (256 threads) ----------------
    __shared__ int hist[1024];
    __shared__ int tsum[256];
    __shared__ unsigned long long cand[512];
    __shared__ int s_ccnt, s_bstar;

    int n = *((volatile int*)&g_nkept);

    #pragma unroll
    for (int q = 0; q < 4; q++) hist[tid * 4 + q] = 0;
    if (tid == 0) { s_ccnt = 0; s_bstar = 0; }
    __syncthreads();

    for (int e = tid; e < n; e += 256) {
        float s = __uint_as_float((unsigned)(g_keptKeys[e] >> 32));
        int b = (int)((s - MIN_CONF) * (1024.0f / 0.3f));
        b = min(1023, max(0, b));
        atomicAdd(&hist[b], 1);
    }
    __syncthreads();

    // Suffix sums over 1024 bins: thread t owns bins [4t..4t+3].
    int h0 = hist[tid * 4 + 0], h1 = hist[tid * 4 + 1];
    int h2 = hist[tid * 4 + 2], h3 = hist[tid * 4 + 3];
    tsum[tid] = h0 + h1 + h2 + h3;
    __syncthreads();
    for (int st = 1; st < 256; st <<= 1) {
        int v = tsum[tid] + ((tid + st < 256) ? tsum[tid + st] : 0);
        __syncthreads();
        tsum[tid] = v;
        __syncthreads();
    }
    int tail = (tid + 1 < 256) ? tsum[tid + 1] : 0;   // suffix past my bins
    int S3 = h3 + tail;
    int S2 = h2 + S3;
    int S1 = h1 + S2;
    int S0 = h0 + S1;
    // Unique boundary: largest b with S(b) >= MAXI and S(b+1) < MAXI.
    if (S0 >= MAXI && S1 < MAXI)                 s_bstar = tid * 4 + 0;
    if (S1 >= MAXI && S2 < MAXI)                 s_bstar = tid * 4 + 1;
    if (S2 >= MAXI && S3 < MAXI)                 s_bstar = tid * 4 + 2;
    if (S3 >= MAXI && (tid == 255 || tail < MAXI)) s_bstar = tid * 4 + 3;
    __syncthreads();
    const int B = s_bstar;

    for (int e = tid; e < n; e += 256) {
        unsigned long long key = g_keptKeys[e];
        float s = __uint_as_float((unsigned)(key >> 32));
        int b = (int)((s - MIN_CONF) * (1024.0f / 0.3f));
        b = min(1023, max(0, b));
        if (b >= B) {
            int pos = atomicAdd(&s_ccnt, 1);
            if (pos < 512) cand[pos] = key;
        }
    }
    __syncthreads();
    int k2 = min(s_ccnt, 512);
    for (int i = tid; i < 512; i += 256)
        if (i >= k2) cand[i] = 0ULL;
    __syncthreads();

    // Bitonic ascending sort of 512 keys with 256 threads.
    for (int kk = 2; kk <= 512; kk <<= 1) {
        for (int j = kk >> 1; j > 0; j >>= 1) {
            for (int i = tid; i < 512; i += 256) {
                int ixj = i ^ j;
                if (ixj > i) {
                    bool up = ((i & kk) == 0);
                    unsigned long long a = cand[i], b = cand[ixj];
                    if ((a > b) == up) { cand[i] = b; cand[ixj] = a; }
                }
            }
            __syncthreads();
        }
    }

    // Emit top-100 (descending), zero-fill the rest.
    if (tid < MAXI) {
        unsigned long long key = cand[511 - tid];
        if (key >> 32) {
            int r = (int)(0xFFFFFFFFu - (unsigned int)(key & 0xFFFFFFFFu));
            out[tid * 6 + 0] = g_box[r * 4 + 0];
            out[tid * 6 + 1] = g_box[r * 4 + 1];
            out[tid * 6 + 2] = g_box[r * 4 + 2];
            out[tid * 6 + 3] = g_box[r * 4 + 3];
            out[tid * 6 + 4] = (float)g_cls[r];
            out[tid * 6 + 5] = g_score[r];
        } else {
            #pragma unroll
            for (int q = 0; q < 6; q++) out[tid * 6 + q] = 0.0f;
        }
    }

    // Reset counters for the next (graph-replayed) launch.
    __syncthreads();
    if (tid < NCLS) g_clsCnt[tid] = 0;
    if (tid == 128) g_nkept = 0;
    if (tid == 129) g_done = 0;
}

extern "C" void kernel_launch(void* const* d_in, const int* in_sizes, int n_in,
                              void* d_out, int out_size)
{
    const float* rois   = (const float*)d_in[0];
    const float* probs  = (const float*)d_in[1];
    const float* deltas = (const float*)d_in[2];
    const float* window = (const float*)d_in[3];
    float* out = (float*)d_out;

    int warpsA  = NBOX / 2;                       // 2500 warps, 2 ROIs each
    int blocksA = (warpsA * 32 + 255) / 256;
    k_refine<<<blocksA, 256>>>(rois, probs, deltas, window);

    k_nms_topk<<<NBLK, 256>>>(out);
}

// round 5
// speedup vs baseline: 1.2698x; 1.0623x over previous
#include <cuda_runtime.h>
#include <cstdint>

#define NBOX      5000
#define NCLS      81
#define MAXI      100
#define CLSMAX    128          // per-class candidate cap (E≈62, σ≈7.8)
#define NBLK      10           // 10 blocks x 8 warps = 80 classes
#define MIN_CONF  0.7f
#define NMS_THR   0.3f

// Persistent scratch; everything consumed is rewritten every launch.
__device__ float              g_box[NBOX * 4];
__device__ float              g_score[NBOX];
__device__ int                g_cls[NBOX];
__device__ unsigned long long g_clsKeys[NCLS * CLSMAX];
__device__ int                g_clsCnt[NCLS];               // reset by last block
__device__ unsigned long long g_keptSeg[80 * MAXI];         // per-class kept keys
__device__ int                g_keptCnt[80];                // written every launch
__device__ int                g_done;                       // reset by last block

// ---------------------------------------------------------------------------
// Kernel A: one warp per 2 ROIs. Argmax over 81 classes (first-max tie-break),
// class-specific delta refine, clip, bucket valid boxes by class.
// ---------------------------------------------------------------------------
__global__ void k_refine(const float* __restrict__ rois,
                         const float* __restrict__ probs,
                         const float* __restrict__ deltas,
                         const float* __restrict__ window)
{
    int w    = (blockIdx.x * blockDim.x + threadIdx.x) >> 5;
    int lane = threadIdx.x & 31;
    if (w >= NBOX / 2) return;

    const int r0 = 2 * w;
    const float* p0 = probs + (size_t)r0 * NCLS;
    const float* p1 = p0 + NCLS;

    float bp0 = -1.0f, bp1 = -1.0f;
    int   bi0 = 0,     bi1 = 0;
    #pragma unroll
    for (int it = 0; it < 3; it++) {
        int c = lane + it * 32;
        if (c < NCLS) {
            float v0 = p0[c];
            float v1 = p1[c];
            if (v0 > bp0) { bp0 = v0; bi0 = c; }
            if (v1 > bp1) { bp1 = v1; bi1 = c; }
        }
    }
    #pragma unroll
    for (int off = 16; off; off >>= 1) {
        float op0 = __shfl_xor_sync(0xffffffffu, bp0, off);
        int   oi0 = __shfl_xor_sync(0xffffffffu, bi0, off);
        float op1 = __shfl_xor_sync(0xffffffffu, bp1, off);
        int   oi1 = __shfl_xor_sync(0xffffffffu, bi1, off);
        if (op0 > bp0 || (op0 == bp0 && oi0 < bi0)) { bp0 = op0; bi0 = oi0; }
        if (op1 > bp1 || (op1 == bp1 && oi1 < bi1)) { bp1 = op1; bi1 = oi1; }
    }

    if (lane < 2) {
        int   r  = r0 + lane;
        float bp = (lane == 0) ? bp0 : bp1;
        int   bi = (lane == 0) ? bi0 : bi1;

        float y1r = rois[r * 4 + 0];
        float x1r = rois[r * 4 + 1];
        float y2r = rois[r * 4 + 2];
        float x2r = rois[r * 4 + 3];
        float h  = y2r - y1r;
        float wd = x2r - x1r;
        float cy = y1r + 0.5f * h;
        float cx = x1r + 0.5f * wd;

        const float* d = deltas + ((size_t)r * NCLS + bi) * 4;
        cy += (d[0] * 0.1f) * h;
        cx += (d[1] * 0.1f) * wd;
        h  *= expf(d[2] * 0.2f);
        wd *= expf(d[3] * 0.2f);

        float y1 = cy - 0.5f * h;
        float x1 = cx - 0.5f * wd;
        float y2 = y1 + h;
        float x2 = x1 + wd;

        float wy1 = window[0], wx1 = window[1], wy2 = window[2], wx2 = window[3];
        y1 = fminf(fmaxf(y1, wy1), wy2);
        x1 = fminf(fmaxf(x1, wx1), wx2);
        y2 = fminf(fmaxf(y2, wy1), wy2);
        x2 = fminf(fmaxf(x2, wx1), wx2);

        g_box[r * 4 + 0] = y1;
        g_box[r * 4 + 1] = x1;
        g_box[r * 4 + 2] = y2;
        g_box[r * 4 + 3] = x2;
        g_score[r] = bp;

        int cls = (bi > 0 && bp >= MIN_CONF) ? bi : 0;
        g_cls[r] = cls;
        if (cls > 0) {
            unsigned long long key =
                ((unsigned long long)__float_as_uint(bp) << 32) |
                (unsigned int)(0xFFFFFFFFu - (unsigned int)r);
            int pos = atomicAdd(&g_clsCnt[cls], 1);
            if (pos < CLSMAX) g_clsKeys[cls * CLSMAX + pos] = key;
        }
    }
}

// ---------------------------------------------------------------------------
// Kernel B: warp-per-class bitmask NMS (no global atomics); the last block to
// finish performs the global top-100 and resets counters.
// ---------------------------------------------------------------------------
__global__ void __launch_bounds__(256) k_nms_topk(float* __restrict__ out)
{
    const int tid  = threadIdx.x;
    const int warp = tid >> 5;
    const int lane = tid & 31;

    __shared__ unsigned long long s_keys[8][CLSMAX];
    __shared__ float s_y1[8][CLSMAX], s_x1[8][CLSMAX];
    __shared__ float s_y2[8][CLSMAX], s_x2[8][CLSMAX], s_ar[8][CLSMAX];
    __shared__ unsigned long long s_m0[8][CLSMAX], s_m1[8][CLSMAX];
    __shared__ int s_last;

    const int cseg = blockIdx.x * 8 + warp;       // 0..79
    const int c    = cseg + 1;                    // class 1..80
    int cnt = min(g_clsCnt[c], CLSMAX);

    if (cnt > 0) {
        for (int t = lane; t < cnt; t += 32)
            s_keys[warp][t] = g_clsKeys[c * CLSMAX + t];

        int m = 2;
        while (m < cnt) m <<= 1;                  // <= 128
        for (int t = lane; t < m; t += 32)
            if (t >= cnt) s_keys[warp][t] = 0ULL;
        __syncwarp();

        // Warp bitonic ascending sort of m keys.
        for (int kk = 2; kk <= m; kk <<= 1) {
            for (int j = kk >> 1; j > 0; j >>= 1) {
                for (int i = lane; i < m; i += 32) {
                    int ixj = i ^ j;
                    if (ixj > i) {
                        bool up = ((i & kk) == 0);
                        unsigned long long a = s_keys[warp][i];
                        unsigned long long b = s_keys[warp][ixj];
                        if ((a > b) == up) { s_keys[warp][i] = b; s_keys[warp][ixj] = a; }
                    }
                }
                __syncwarp();
            }
        }

        // Boxes in descending (score, -idx) order.
        for (int t = lane; t < cnt; t += 32) {
            unsigned long long key = s_keys[warp][m - 1 - t];
            int r = (int)(0xFFFFFFFFu - (unsigned int)(key & 0xFFFFFFFFu));
            float y1 = g_box[r * 4 + 0];
            float x1 = g_box[r * 4 + 1];
            float y2 = g_box[r * 4 + 2];
            float x2 = g_box[r * 4 + 3];
            s_y1[warp][t] = y1; s_x1[warp][t] = x1;
            s_y2[warp][t] = y2; s_x2[warp][t] = x2;
            s_ar[warp][t] = fmaxf(y2 - y1, 0.0f) * fmaxf(x2 - x1, 0.0f);
        }
        __syncwarp();

        // Parallel overlap bit-matrix: row i gets bit j (j<i) if IoU > thr.
        for (int i = lane; i < cnt; i += 32) {
            float iy1 = s_y1[warp][i], ix1 = s_x1[warp][i];
            float iy2 = s_y2[warp][i], ix2 = s_x2[warp][i];
            float ia  = s_ar[warp][i];
            unsigned long long m0 = 0ULL, m1 = 0ULL;
            for (int j = 0; j < i; j++) {
                float yy1 = fmaxf(iy1, s_y1[warp][j]);
                float xx1 = fmaxf(ix1, s_x1[warp][j]);
                float yy2 = fminf(iy2, s_y2[warp][j]);
                float xx2 = fminf(ix2, s_x2[warp][j]);
                float inter = fmaxf(yy2 - yy1, 0.0f) * fmaxf(xx2 - xx1, 0.0f);
                float uni   = ia + s_ar[warp][j] - inter;
                // iou > THR  <=>  uni>0 && inter > THR*max(uni,1e-12)
                if (uni > 0.0f && inter > NMS_THR * fmaxf(uni, 1e-12f)) {
                    if (j < 64) m0 |= 1ULL << j;
                    else        m1 |= 1ULL << (j - 64);
                }
            }
            s_m0[warp][i] = m0;
            s_m1[warp][i] = m1;
        }
        __syncwarp();

        // Serial greedy sweep, replicated in every lane (pure ALU, prefetched).
        unsigned long long kept0 = 0ULL, kept1 = 0ULL;
        int cntK = 0;
        unsigned long long nm0 = s_m0[warp][0], nm1 = s_m1[warp][0];
        for (int i = 0; i < cnt; i++) {
            unsigned long long m0 = nm0, m1 = nm1;
            if (i + 1 < cnt) { nm0 = s_m0[warp][i + 1]; nm1 = s_m1[warp][i + 1]; }
            bool ok = (((m0 & kept0) | (m1 & kept1)) == 0ULL) && (cntK < MAXI);
            if (ok) {
                if (i < 64) kept0 |= 1ULL << i;
                else        kept1 |= 1ULL << (i - 64);
                cntK++;
            }
        }

        // Emit kept keys in rank order (no atomics; warp owns its segment).
        for (int t = lane; t < cnt; t += 32) {
            bool isKept = (t < 64) ? ((kept0 >> t) & 1ULL)
                                   : ((kept1 >> (t - 64)) & 1ULL);
            if (isKept) {
                int rank;
                if (t < 64) rank = __popcll(kept0 & ((1ULL << t) - 1ULL));
                else        rank = __popcll(kept0) +
                                   __popcll(kept1 & ((1ULL << (t - 64)) - 1ULL));
                g_keptSeg[cseg * MAXI + rank] = s_keys[warp][m - 1 - t];
            }
        }
        if (lane == 0) g_keptCnt[cseg] = cntK;
    } else {
        if (lane == 0) g_keptCnt[cseg] = 0;
    }

    // ---- last-block handoff ----
    __syncthreads();
    if (tid == 0) {
        __threadfence();
        int prev = atomicAdd(&g_done, 1);
        s_last = (prev == NBLK - 1);
    }
    __syncthreads();
    if (!s_last) return;

    // ---------------- global top-100 (256 threads) ----------------
    __shared__ int hist[1024];
    __shared__ int tsum[256];
    __shared__ unsigned long long cand[512];
    __shared__ int s_kcnt[80];
    __shared__ int s_ccnt, s_bstar;

    if (tid < 80) s_kcnt[tid] = *((volatile int*)&g_keptCnt[tid]);
    #pragma unroll
    for (int q = 0; q < 4; q++) hist[tid * 4 + q] = 0;
    if (tid == 0) { s_ccnt = 0; s_bstar = 0; }
    __syncthreads();

    // Histogram over all kept keys (80 segments).
    for (int s = tid; s < 80 * MAXI; s += 256) {
        int seg = s / MAXI, k = s - seg * MAXI;
        if (k < s_kcnt[seg]) {
            float sc = __uint_as_float((unsigned)(g_keptSeg[s] >> 32));
            int b = (int)((sc - MIN_CONF) * (1024.0f / 0.3f));
            b = min(1023, max(0, b));
            atomicAdd(&hist[b], 1);
        }
    }
    __syncthreads();

    // Suffix sums over 1024 bins: thread t owns bins [4t..4t+3].
    int h0 = hist[tid * 4 + 0], h1 = hist[tid * 4 + 1];
    int h2 = hist[tid * 4 + 2], h3 = hist[tid * 4 + 3];
    tsum[tid] = h0 + h1 + h2 + h3;
    __syncthreads();
    for (int st = 1; st < 256; st <<= 1) {
        int v = tsum[tid] + ((tid + st < 256) ? tsum[tid + st] : 0);
        __syncthreads();
        tsum[tid] = v;
        __syncthreads();
    }
    int tail = (tid + 1 < 256) ? tsum[tid + 1] : 0;
    int S3 = h3 + tail;
    int S2 = h2 + S3;
    int S1 = h1 + S2;
    int S0 = h0 + S1;
    if (S0 >= MAXI && S1 < MAXI)                   s_bstar = tid * 4 + 0;
    if (S1 >= MAXI && S2 < MAXI)                   s_bstar = tid * 4 + 1;
    if (S2 >= MAXI && S3 < MAXI)                   s_bstar = tid * 4 + 2;
    if (S3 >= MAXI && (tid == 255 || tail < MAXI)) s_bstar = tid * 4 + 3;
    __syncthreads();
    const int B = s_bstar;

    // Collect candidates above threshold bin (order restored by full sort).
    for (int s = tid; s < 80 * MAXI; s += 256) {
        int seg = s / MAXI, k = s - seg * MAXI;
        if (k < s_kcnt[seg]) {
            unsigned long long key = g_keptSeg[s];
            float sc = __uint_as_float((unsigned)(key >> 32));
            int b = (int)((sc - MIN_CONF) * (1024.0f / 0.3f));
            b = min(1023, max(0, b));
            if (b >= B) {
                int pos = atomicAdd(&s_ccnt, 1);
                if (pos < 512) cand[pos] = key;
            }
        }
    }
    __syncthreads();
    int k2 = min(s_ccnt, 512);
    for (int i = tid; i < 512; i += 256)
        if (i >= k2) cand[i] = 0ULL;
    __syncthreads();

    // Bitonic ascending sort of 512 keys with 256 threads.
    for (int kk = 2; kk <= 512; kk <<= 1) {
        for (int j = kk >> 1; j > 0; j >>= 1) {
            for (int i = tid; i < 512; i += 256) {
                int ixj = i ^ j;
                if (ixj > i) {
                    bool up = ((i & kk) == 0);
                    unsigned long long a = cand[i], b = cand[ixj];
                    if ((a > b) == up) { cand[i] = b; cand[ixj] = a; }
                }
            }
            __syncthreads();
        }
    }

    // Emit top-100 (descending), zero-fill the rest.
    if (tid < MAXI) {
        unsigned long long key = cand[511 - tid];
        if (key >> 32) {
            int r = (int)(0xFFFFFFFFu - (unsigned int)(key & 0xFFFFFFFFu));
            out[tid * 6 + 0] = g_box[r * 4 + 0];
            out[tid * 6 + 1] = g_box[r * 4 + 1];
            out[tid * 6 + 2] = g_box[r * 4 + 2];
            out[tid * 6 + 3] = g_box[r * 4 + 3];
            out[tid * 6 + 4] = (float)g_cls[r];
            out[tid * 6 + 5] = g_score[r];
        } else {
            #pragma unroll
            for (int q = 0; q < 6; q++) out[tid * 6 + q] = 0.0f;
        }
    }

    // Reset counters for the next (graph-replayed) launch.
    __syncthreads();
    if (tid < NCLS) g_clsCnt[tid] = 0;
    if (tid == 128) g_done = 0;
}

extern "C" void kernel_launch(void* const* d_in, const int* in_sizes, int n_in,
                              void* d_out, int out_size)
{
    const float* rois   = (const float*)d_in[0];
    const float* probs  = (const float*)d_in[1];
    const float* deltas = (const float*)d_in[2];
    const float* window = (const float*)d_in[3];
    float* out = (float*)d_out;

    int warpsA  = NBOX / 2;
    int blocksA = (warpsA * 32 + 255) / 256;
    k_refine<<<blocksA, 256>>>(rois, probs, deltas, window);

    k_nms_topk<<<NBLK, 256>>>(out);
}

// round 7
// speedup vs baseline: 1.2789x; 1.0071x over previous
#include <cuda_runtime.h>
#include <cstdint>

#define NBOX      5000
#define NCLS      81
#define MAXI      100
#define CLSMAX    128
#define GRID      90           // <= 148 SMs -> all blocks co-resident (spin-safe)
#define TPB       256
#define NMSBLK    10           // blocks 0..9 run NMS (80 warps = 80 classes)
#define MIN_CONF  0.7f
#define NMS_THR   0.3f

// Persistent scratch. All counters are zero at load and re-zeroed by block 0
// at the end of every launch -> deterministic across graph replays.
__device__ float              g_box[NBOX * 4];
__device__ float              g_score[NBOX];
__device__ int                g_cls[NBOX];
__device__ unsigned long long g_clsKeys[NCLS * CLSMAX];
__device__ int                g_clsCnt[NCLS];
__device__ unsigned long long g_keptSeg[80 * MAXI];
__device__ int                g_keptCnt[80];
__device__ int                g_bar1;
__device__ int                g_bar2;

__global__ void __launch_bounds__(TPB)
k_all(const float* __restrict__ rois,
      const float* __restrict__ probs,
      const float* __restrict__ deltas,
      const float* __restrict__ window,
      float* __restrict__ out)
{
    const int tid  = threadIdx.x;
    const int warp = tid >> 5;
    const int lane = tid & 31;
    const int gw   = blockIdx.x * (TPB / 32) + warp;   // 0..719

    // ======================= Phase 1: refine (all blocks) ===================
    const float wy1 = window[0], wx1 = window[1];
    const float wy2 = window[2], wx2 = window[3];

    for (int pair = gw; pair < NBOX / 2; pair += GRID * (TPB / 32)) {
        const int r0 = 2 * pair;
        const float* p0 = probs + (size_t)r0 * NCLS;
        const float* p1 = p0 + NCLS;

        float bp0 = -1.0f, bp1 = -1.0f;
        int   bi0 = 0,     bi1 = 0;
        #pragma unroll
        for (int it = 0; it < 3; it++) {
            int c = lane + it * 32;
            if (c < NCLS) {
                float v0 = p0[c];
                float v1 = p1[c];
                if (v0 > bp0) { bp0 = v0; bi0 = c; }
                if (v1 > bp1) { bp1 = v1; bi1 = c; }
            }
        }
        #pragma unroll
        for (int off = 16; off; off >>= 1) {
            float op0 = __shfl_xor_sync(0xffffffffu, bp0, off);
            int   oi0 = __shfl_xor_sync(0xffffffffu, bi0, off);
            float op1 = __shfl_xor_sync(0xffffffffu, bp1, off);
            int   oi1 = __shfl_xor_sync(0xffffffffu, bi1, off);
            if (op0 > bp0 || (op0 == bp0 && oi0 < bi0)) { bp0 = op0; bi0 = oi0; }
            if (op1 > bp1 || (op1 == bp1 && oi1 < bi1)) { bp1 = op1; bi1 = oi1; }
        }

        if (lane < 2) {
            int   r  = r0 + lane;
            float bp = (lane == 0) ? bp0 : bp1;
            int   bi = (lane == 0) ? bi0 : bi1;

            float y1r = rois[r * 4 + 0];
            float x1r = rois[r * 4 + 1];
            float y2r = rois[r * 4 + 2];
            float x2r = rois[r * 4 + 3];
            float h  = y2r - y1r;
            float wd = x2r - x1r;
            float cy = y1r + 0.5f * h;
            float cx = x1r + 0.5f * wd;

            const float* d = deltas + ((size_t)r * NCLS + bi) * 4;
            cy += (d[0] * 0.1f) * h;
            cx += (d[1] * 0.1f) * wd;
            h  *= expf(d[2] * 0.2f);
            wd *= expf(d[3] * 0.2f);

            float y1 = cy - 0.5f * h;
            float x1 = cx - 0.5f * wd;
            float y2 = y1 + h;
            float x2 = x1 + wd;

            y1 = fminf(fmaxf(y1, wy1), wy2);
            x1 = fminf(fmaxf(x1, wx1), wx2);
            y2 = fminf(fmaxf(y2, wy1), wy2);
            x2 = fminf(fmaxf(x2, wx1), wx2);

            g_box[r * 4 + 0] = y1;
            g_box[r * 4 + 1] = x1;
            g_box[r * 4 + 2] = y2;
            g_box[r * 4 + 3] = x2;
            g_score[r] = bp;

            int cls = (bi > 0 && bp >= MIN_CONF) ? bi : 0;
            g_cls[r] = cls;
            if (cls > 0) {
                unsigned long long key =
                    ((unsigned long long)__float_as_uint(bp) << 32) |
                    (unsigned int)(0xFFFFFFFFu - (unsigned int)r);
                int pos = atomicAdd(&g_clsCnt[cls], 1);
                if (pos < CLSMAX) g_clsKeys[cls * CLSMAX + pos] = key;
            }
        }
    }

    // ---- global barrier 1 (arrive; only blocks 0..9 wait) ----
    __syncthreads();
    if (tid == 0) {
        __threadfence();
        atomicAdd(&g_bar1, 1);
    }
    if (blockIdx.x >= NMSBLK) return;

    if (tid == 0) {
        while (*((volatile int*)&g_bar1) < GRID) { }
    }
    __syncthreads();
    __threadfence();

    // ================= Phase 2: NMS (blocks 0..9, warp/class) ==============
    __shared__ unsigned long long s_keys[8][CLSMAX];
    __shared__ float s_y1[8][CLSMAX], s_x1[8][CLSMAX];
    __shared__ float s_y2[8][CLSMAX], s_x2[8][CLSMAX], s_ar[8][CLSMAX];
    __shared__ unsigned long long s_m0[8][CLSMAX], s_m1[8][CLSMAX];

    const int cseg = blockIdx.x * 8 + warp;   // 0..79
    const int c    = cseg + 1;                // class 1..80
    int cnt = min(g_clsCnt[c], CLSMAX);

    if (cnt > 0) {
        for (int t = lane; t < cnt; t += 32)
            s_keys[warp][t] = g_clsKeys[c * CLSMAX + t];

        int m = 2;
        while (m < cnt) m <<= 1;              // typ. 64
        for (int t = lane; t < m; t += 32)
            if (t >= cnt) s_keys[warp][t] = 0ULL;
        __syncwarp();

        for (int kk = 2; kk <= m; kk <<= 1) {
            for (int j = kk >> 1; j > 0; j >>= 1) {
                for (int i = lane; i < m; i += 32) {
                    int ixj = i ^ j;
                    if (ixj > i) {
                        bool up = ((i & kk) == 0);
                        unsigned long long a = s_keys[warp][i];
                        unsigned long long b = s_keys[warp][ixj];
                        if ((a > b) == up) { s_keys[warp][i] = b; s_keys[warp][ixj] = a; }
                    }
                }
                __syncwarp();
            }
        }

        for (int t = lane; t < cnt; t += 32) {
            unsigned long long key = s_keys[warp][m - 1 - t];
            int r = (int)(0xFFFFFFFFu - (unsigned int)(key & 0xFFFFFFFFu));
            float y1 = g_box[r * 4 + 0];
            float x1 = g_box[r * 4 + 1];
            float y2 = g_box[r * 4 + 2];
            float x2 = g_box[r * 4 + 3];
            s_y1[warp][t] = y1; s_x1[warp][t] = x1;
            s_y2[warp][t] = y2; s_x2[warp][t] = x2;
            s_ar[warp][t] = fmaxf(y2 - y1, 0.0f) * fmaxf(x2 - x1, 0.0f);
        }
        __syncwarp();

        // Overlap bit-matrix: row i, bit j (j<i) set iff IoU > thr.
        for (int i = lane; i < cnt; i += 32) {
            float iy1 = s_y1[warp][i], ix1 = s_x1[warp][i];
            float iy2 = s_y2[warp][i], ix2 = s_x2[warp][i];
            float ia  = s_ar[warp][i];
            unsigned long long m0 = 0ULL, m1 = 0ULL;
            for (int j = 0; j < i; j++) {
                float yy1 = fmaxf(iy1, s_y1[warp][j]);
                float xx1 = fmaxf(ix1, s_x1[warp][j]);
                float yy2 = fminf(iy2, s_y2[warp][j]);
                float xx2 = fminf(ix2, s_x2[warp][j]);
                float inter = fmaxf(yy2 - yy1, 0.0f) * fmaxf(xx2 - xx1, 0.0f);
                float uni   = ia + s_ar[warp][j] - inter;
                if (uni > 0.0f && inter > NMS_THR * fmaxf(uni, 1e-12f)) {
                    if (j < 64) m0 |= 1ULL << j;
                    else        m1 |= 1ULL << (j - 64);
                }
            }
            s_m0[warp][i] = m0;
            s_m1[warp][i] = m1;
        }
        __syncwarp();

        // Serial greedy sweep (replicated per lane; prefetched, pure ALU).
        unsigned long long kept0 = 0ULL, kept1 = 0ULL;
        int cntK = 0;
        unsigned long long nm0 = s_m0[warp][0], nm1 = s_m1[warp][0];
        for (int i = 0; i < cnt; i++) {
            unsigned long long m0 = nm0, m1 = nm1;
            if (i + 1 < cnt) { nm0 = s_m0[warp][i + 1]; nm1 = s_m1[warp][i + 1]; }
            bool ok = (((m0 & kept0) | (m1 & kept1)) == 0ULL) && (cntK < MAXI);
            if (ok) {
                if (i < 64) kept0 |= 1ULL << i;
                else        kept1 |= 1ULL << (i - 64);
                cntK++;
            }
        }

        for (int t = lane; t < cnt; t += 32) {
            bool isKept = (t < 64) ? ((kept0 >> t) & 1ULL)
                                   : ((kept1 >> (t - 64)) & 1ULL);
            if (isKept) {
                int rank;
                if (t < 64) rank = __popcll(kept0 & ((1ULL << t) - 1ULL));
                else        rank = __popcll(kept0) +
                                   __popcll(kept1 & ((1ULL << (t - 64)) - 1ULL));
                g_keptSeg[cseg * MAXI + rank] = s_keys[warp][m - 1 - t];
            }
        }
        if (lane == 0) g_keptCnt[cseg] = cntK;
    } else {
        if (lane == 0) g_keptCnt[cseg] = 0;
    }

    // ---- barrier 2 (10 NMS blocks; only block 0 waits) ----
    __syncthreads();
    if (tid == 0) {
        __threadfence();
        atomicAdd(&g_bar2, 1);
    }
    if (blockIdx.x != 0) return;

    if (tid == 0) {
        while (*((volatile int*)&g_bar2) < NMSBLK) { }
    }
    __syncthreads();
    __threadfence();

    // ==================== Phase 3: top-100 (block 0) ========================
    __shared__ int hist[1024];
    __shared__ int tsum[256];
    __shared__ unsigned long long cand[512];
    __shared__ int s_kcnt[80];
    __shared__ int s_ccnt, s_bstar;

    if (tid < 80) s_kcnt[tid] = g_keptCnt[tid];
    #pragma unroll
    for (int q = 0; q < 4; q++) hist[tid * 4 + q] = 0;
    if (tid == 0) { s_ccnt = 0; s_bstar = 0; }
    __syncthreads();

    for (int s = tid; s < 80 * MAXI; s += 256) {
        int seg = s / MAXI, k = s - seg * MAXI;
        if (k < s_kcnt[seg]) {
            float sc = __uint_as_float((unsigned)(g_keptSeg[s] >> 32));
            int b = (int)((sc - MIN_CONF) * (1024.0f / 0.3f));
            b = min(1023, max(0, b));
            atomicAdd(&hist[b], 1);
        }
    }
    __syncthreads();

    int h0 = hist[tid * 4 + 0], h1 = hist[tid * 4 + 1];
    int h2 = hist[tid * 4 + 2], h3 = hist[tid * 4 + 3];
    tsum[tid] = h0 + h1 + h2 + h3;
    __syncthreads();
    for (int st = 1; st < 256; st <<= 1) {
        int v = tsum[tid] + ((tid + st < 256) ? tsum[tid + st] : 0);
        __syncthreads();
        tsum[tid] = v;
        __syncthreads();
    }
    int tail = (tid + 1 < 256) ? tsum[tid + 1] : 0;
    int S3 = h3 + tail;
    int S2 = h2 + S3;
    int S1 = h1 + S2;
    int S0 = h0 + S1;
    if (S0 >= MAXI && S1 < MAXI)                   s_bstar = tid * 4 + 0;
    if (S1 >= MAXI && S2 < MAXI)                   s_bstar = tid * 4 + 1;
    if (S2 >= MAXI && S3 < MAXI)                   s_bstar = tid * 4 + 2;
    if (S3 >= MAXI && (tid == 255 || tail < MAXI)) s_bstar = tid * 4 + 3;
    __syncthreads();
    const int B = s_bstar;

    for (int s = tid; s < 80 * MAXI; s += 256) {
        int seg = s / MAXI, k = s - seg * MAXI;
        if (k < s_kcnt[seg]) {
            unsigned long long key = g_keptSeg[s];
            float sc = __uint_as_float((unsigned)(key >> 32));
            int b = (int)((sc - MIN_CONF) * (1024.0f / 0.3f));
            b = min(1023, max(0, b));
            if (b >= B) {
                int pos = atomicAdd(&s_ccnt, 1);
                if (pos < 512) cand[pos] = key;
            }
        }
    }
    __syncthreads();
    int k2 = min(s_ccnt, 512);
    int m2 = 128;                          // >= MAXI candidates guaranteed
    while (m2 < k2) m2 <<= 1;              // typ. 128
    for (int i = tid; i < m2; i += 256)
        if (i >= k2) cand[i] = 0ULL;
    __syncthreads();

    for (int kk = 2; kk <= m2; kk <<= 1) {
        for (int j = kk >> 1; j > 0; j >>= 1) {
            for (int i = tid; i < m2; i += 256) {
                int ixj = i ^ j;
                if (ixj > i) {
                    bool up = ((i & kk) == 0);
                    unsigned long long a = cand[i], b = cand[ixj];
                    if ((a > b) == up) { cand[i] = b; cand[ixj] = a; }
                }
            }
            __syncthreads();
        }
    }

    if (tid < MAXI) {
        unsigned long long key = cand[m2 - 1 - tid];
        if (key >> 32) {
            int r = (int)(0xFFFFFFFFu - (unsigned int)(key & 0xFFFFFFFFu));
            out[tid * 6 + 0] = g_box[r * 4 + 0];
            out[tid * 6 + 1] = g_box[r * 4 + 1];
            out[tid * 6 + 2] = g_box[r * 4 + 2];
            out[tid * 6 + 3] = g_box[r * 4 + 3];
            out[tid * 6 + 4] = (float)g_cls[r];
            out[tid * 6 + 5] = g_score[r];
        } else {
            #pragma unroll
            for (int q = 0; q < 6; q++) out[tid * 6 + q] = 0.0f;
        }
    }

    // Reset all counters for the next (graph-replayed) launch.
    __syncthreads();
    if (tid < NCLS) g_clsCnt[tid] = 0;
    if (tid == 128) g_bar1 = 0;
    if (tid == 129) g_bar2 = 0;
}

extern "C" void kernel_launch(void* const* d_in, const int* in_sizes, int n_in,
                              void* d_out, int out_size)
{
    const float* rois   = (const float*)d_in[0];
    const float* probs  = (const float*)d_in[1];
    const float* deltas = (const float*)d_in[2];
    const float* window = (const float*)d_in[3];
    float* out = (float*)d_out;

    k_all<<<GRID, TPB>>>(rois, probs, deltas, window, out);
}

// round 8
// speedup vs baseline: 1.5222x; 1.1903x over previous
#include <cuda_runtime.h>
#include <cstdint>

#define NBOX      5000
#define NCLS      81
#define MAXI      100
#define CLSMAX    128
#define GRID      125          // <= 148 SMs -> all blocks co-resident (spin-safe)
#define TPB       256
#define NMSBLK    10           // blocks 0..9 run NMS (80 warps = 80 classes)
#define CANDCAP   512
#define MIN_CONF  0.7f
#define NMS_THR   0.3f

// Persistent scratch. All counters zero at load; re-zeroed by block 0 at the
// end of every launch -> deterministic across graph replays.
__device__ float4             g_box4[NBOX];
__device__ int                g_cls[NBOX];
__device__ unsigned long long g_clsKeys[NCLS * CLSMAX];
__device__ int                g_clsCnt[NCLS];
__device__ unsigned long long g_keptSeg[80 * MAXI];
__device__ int                g_keptCnt[80];
__device__ int                g_hist[1024];
__device__ int                g_bar1;
__device__ int                g_bar2;

__device__ __forceinline__ int score_bin(float s) {
    int b = (int)((s - MIN_CONF) * (1024.0f / 0.3f));
    return min(1023, max(0, b));
}

__global__ void __launch_bounds__(TPB)
k_all(const float* __restrict__ rois,
      const float* __restrict__ probs,
      const float* __restrict__ deltas,
      const float* __restrict__ window,
      float* __restrict__ out)
{
    const int tid  = threadIdx.x;
    const int warp = tid >> 5;
    const int lane = tid & 31;
    const int gw   = blockIdx.x * (TPB / 32) + warp;   // 0..999

    // ======================= Phase 1: refine (all blocks) ===================
    const float wy1 = window[0], wx1 = window[1];
    const float wy2 = window[2], wx2 = window[3];

    for (int pair = gw; pair < NBOX / 2; pair += GRID * (TPB / 32)) {
        const int r0 = 2 * pair;
        const float* p0 = probs + (size_t)r0 * NCLS;
        const float* p1 = p0 + NCLS;

        float bp0 = -1.0f, bp1 = -1.0f;
        int   bi0 = 0,     bi1 = 0;
        #pragma unroll
        for (int it = 0; it < 3; it++) {
            int c = lane + it * 32;
            if (c < NCLS) {
                float v0 = p0[c];
                float v1 = p1[c];
                if (v0 > bp0) { bp0 = v0; bi0 = c; }
                if (v1 > bp1) { bp1 = v1; bi1 = c; }
            }
        }
        #pragma unroll
        for (int off = 16; off; off >>= 1) {
            float op0 = __shfl_xor_sync(0xffffffffu, bp0, off);
            int   oi0 = __shfl_xor_sync(0xffffffffu, bi0, off);
            float op1 = __shfl_xor_sync(0xffffffffu, bp1, off);
            int   oi1 = __shfl_xor_sync(0xffffffffu, bi1, off);
            if (op0 > bp0 || (op0 == bp0 && oi0 < bi0)) { bp0 = op0; bi0 = oi0; }
            if (op1 > bp1 || (op1 == bp1 && oi1 < bi1)) { bp1 = op1; bi1 = oi1; }
        }

        if (lane < 2) {
            int   r  = r0 + lane;
            float bp = (lane == 0) ? bp0 : bp1;
            int   bi = (lane == 0) ? bi0 : bi1;

            float y1r = rois[r * 4 + 0];
            float x1r = rois[r * 4 + 1];
            float y2r = rois[r * 4 + 2];
            float x2r = rois[r * 4 + 3];
            float h  = y2r - y1r;
            float wd = x2r - x1r;
            float cy = y1r + 0.5f * h;
            float cx = x1r + 0.5f * wd;

            const float* d = deltas + ((size_t)r * NCLS + bi) * 4;
            cy += (d[0] * 0.1f) * h;
            cx += (d[1] * 0.1f) * wd;
            h  *= expf(d[2] * 0.2f);
            wd *= expf(d[3] * 0.2f);

            float y1 = cy - 0.5f * h;
            float x1 = cx - 0.5f * wd;
            float y2 = y1 + h;
            float x2 = x1 + wd;

            y1 = fminf(fmaxf(y1, wy1), wy2);
            x1 = fminf(fmaxf(x1, wx1), wx2);
            y2 = fminf(fmaxf(y2, wy1), wy2);
            x2 = fminf(fmaxf(x2, wx1), wx2);

            g_box4[r] = make_float4(y1, x1, y2, x2);

            int cls = (bi > 0 && bp >= MIN_CONF) ? bi : 0;
            g_cls[r] = cls;
            if (cls > 0) {
                unsigned long long key =
                    ((unsigned long long)__float_as_uint(bp) << 32) |
                    (unsigned int)(0xFFFFFFFFu - (unsigned int)r);
                int pos = atomicAdd(&g_clsCnt[cls], 1);
                if (pos < CLSMAX) g_clsKeys[cls * CLSMAX + pos] = key;
            }
        }
    }

    // ---- global barrier 1 (arrive; only blocks 0..9 wait) ----
    __syncthreads();
    if (tid == 0) {
        __threadfence();
        atomicAdd(&g_bar1, 1);
    }
    if (blockIdx.x >= NMSBLK) return;

    if (tid == 0) {
        while (*((volatile int*)&g_bar1) < GRID) { }
    }
    __syncthreads();
    __threadfence();

    // ================= Phase 2: NMS (blocks 0..9, warp/class) ==============
    __shared__ unsigned long long s_keys[8][CLSMAX];
    __shared__ unsigned long long s_sorted[8][CLSMAX];
    __shared__ float4 s_box[8][CLSMAX];
    __shared__ float  s_ar[8][CLSMAX];
    __shared__ unsigned long long s_m0[8][CLSMAX], s_m1[8][CLSMAX];

    const int cseg = blockIdx.x * 8 + warp;   // 0..79
    const int c    = cseg + 1;                // class 1..80
    int cnt = min(g_clsCnt[c], CLSMAX);

    if (cnt > 0) {
        for (int t = lane; t < cnt; t += 32)
            s_keys[warp][t] = g_clsKeys[c * CLSMAX + t];
        __syncwarp();

        // Rank-sort into descending order: rank = #{keys greater}. Keys are
        // unique (idx embedded) -> ranks are a permutation.
        for (int t = lane; t < cnt; t += 32) {
            unsigned long long k = s_keys[warp][t];
            int r = 0;
            for (int j = 0; j < cnt; j++) r += (s_keys[warp][j] > k);
            s_sorted[warp][r] = k;
        }
        __syncwarp();

        // Boxes in rank order.
        for (int t = lane; t < cnt; t += 32) {
            int r = (int)(0xFFFFFFFFu - (unsigned int)(s_sorted[warp][t] & 0xFFFFFFFFu));
            float4 b = g_box4[r];
            s_box[warp][t] = b;
            s_ar[warp][t]  = fmaxf(b.z - b.x, 0.0f) * fmaxf(b.w - b.y, 0.0f);
        }
        __syncwarp();

        // Overlap bit-matrix; rows paired (i, cnt-1-i) for balance.
        int half = (cnt + 1) >> 1;
        for (int p = lane; p < half; p += 32) {
            #pragma unroll
            for (int side = 0; side < 2; side++) {
                int i = side ? (cnt - 1 - p) : p;
                if (side && i == p) break;
                float4 bi = s_box[warp][i];
                float  ia = s_ar[warp][i];
                unsigned long long m0 = 0ULL, m1 = 0ULL;
                for (int j = 0; j < i; j++) {
                    float4 bj = s_box[warp][j];
                    float yy1 = fmaxf(bi.x, bj.x);
                    float xx1 = fmaxf(bi.y, bj.y);
                    float yy2 = fminf(bi.z, bj.z);
                    float xx2 = fminf(bi.w, bj.w);
                    float inter = fmaxf(yy2 - yy1, 0.0f) * fmaxf(xx2 - xx1, 0.0f);
                    float uni   = ia + s_ar[warp][j] - inter;
                    // iou > THR  <=>  uni>0 && inter > THR*max(uni,1e-12)
                    if (uni > 0.0f && inter > NMS_THR * fmaxf(uni, 1e-12f)) {
                        if (j < 64) m0 |= 1ULL << j;
                        else        m1 |= 1ULL << (j - 64);
                    }
                }
                s_m0[warp][i] = m0;
                s_m1[warp][i] = m1;
            }
        }
        __syncwarp();

        // Serial greedy sweep (replicated per lane; prefetched, pure ALU).
        unsigned long long kept0 = 0ULL, kept1 = 0ULL;
        int cntK = 0;
        unsigned long long nm0 = s_m0[warp][0], nm1 = s_m1[warp][0];
        for (int i = 0; i < cnt; i++) {
            unsigned long long m0 = nm0, m1 = nm1;
            if (i + 1 < cnt) { nm0 = s_m0[warp][i + 1]; nm1 = s_m1[warp][i + 1]; }
            bool ok = (((m0 & kept0) | (m1 & kept1)) == 0ULL) && (cntK < MAXI);
            if (ok) {
                if (i < 64) kept0 |= 1ULL << i;
                else        kept1 |= 1ULL << (i - 64);
                cntK++;
            }
        }

        // Emit kept keys (rank order) + histogram contribution (RED, no return).
        for (int t = lane; t < cnt; t += 32) {
            bool isKept = (t < 64) ? ((kept0 >> t) & 1ULL)
                                   : ((kept1 >> (t - 64)) & 1ULL);
            if (isKept) {
                int rank;
                if (t < 64) rank = __popcll(kept0 & ((1ULL << t) - 1ULL));
                else        rank = __popcll(kept0) +
                                   __popcll(kept1 & ((1ULL << (t - 64)) - 1ULL));
                unsigned long long key = s_sorted[warp][t];
                g_keptSeg[cseg * MAXI + rank] = key;
                float sc = __uint_as_float((unsigned)(key >> 32));
                atomicAdd(&g_hist[score_bin(sc)], 1);
            }
        }
        if (lane == 0) g_keptCnt[cseg] = cntK;
    } else {
        if (lane == 0) g_keptCnt[cseg] = 0;
    }

    // ---- barrier 2 (10 NMS blocks; only block 0 waits) ----
    __syncthreads();
    if (tid == 0) {
        __threadfence();
        atomicAdd(&g_bar2, 1);
    }
    if (blockIdx.x != 0) return;

    if (tid == 0) {
        while (*((volatile int*)&g_bar2) < NMSBLK) { }
    }
    __syncthreads();
    __threadfence();

    // ==================== Phase 3: top-100 (block 0) ========================
    __shared__ int s_hist[1024];
    __shared__ unsigned long long cand[CANDCAP];
    __shared__ int s_kcnt[80];
    __shared__ int s_ccnt, s_bstar;

    // Load histogram (and clear it for next launch), zero-fill output rows.
    #pragma unroll
    for (int q = 0; q < 4; q++) {
        int b = tid * 4 + q;
        s_hist[b] = g_hist[b];
        g_hist[b] = 0;
    }
    if (tid < 80) s_kcnt[tid] = g_keptCnt[tid];
    if (tid == 0) { s_ccnt = 0; s_bstar = 0; }
    if (tid < MAXI) {
        #pragma unroll
        for (int q = 0; q < 6; q++) out[tid * 6 + q] = 0.0f;
    }
    __syncthreads();

    // Warp 0: suffix-scan 1024 bins, find threshold bin B such that
    // S(B) >= MAXI > S(B+1)  (S = count of kept with bin >= b).
    if (warp == 0) {
        int base = lane * 32;
        int csum = 0;
        #pragma unroll
        for (int b = 0; b < 32; b++) csum += s_hist[base + b];
        int v = csum;
        #pragma unroll
        for (int off = 1; off < 32; off <<= 1) {
            int t = __shfl_down_sync(0xffffffffu, v, off);
            if (lane + off < 32) v += t;
        }
        int running = v - csum;               // S(base+32) = sum of higher chunks
        for (int b = 31; b >= 0; b--) {
            int S = running + s_hist[base + b];
            if (S >= MAXI && running < MAXI) s_bstar = base + b;
            running = S;
        }
    }
    __syncthreads();
    const int B = s_bstar;

    // Collect candidates with bin >= B.
    for (int s = tid; s < 80 * MAXI; s += 256) {
        int seg = s / MAXI, k = s - seg * MAXI;
        if (k < s_kcnt[seg]) {
            unsigned long long key = g_keptSeg[s];
            float sc = __uint_as_float((unsigned)(key >> 32));
            if (score_bin(sc) >= B) {
                int pos = atomicAdd(&s_ccnt, 1);
                if (pos < CANDCAP) cand[pos] = key;
            }
        }
    }
    __syncthreads();
    int k2 = min(s_ccnt, CANDCAP);

    // Rank-select: rank = #{keys greater}; unique keys -> unique ranks.
    for (int t = tid; t < k2; t += 256) {
        unsigned long long key = cand[t];
        int rank = 0;
        for (int j = 0; j < k2; j++) rank += (cand[j] > key);
        if (rank < MAXI) {
            int r = (int)(0xFFFFFFFFu - (unsigned int)(key & 0xFFFFFFFFu));
            float4 b4 = g_box4[r];
            out[rank * 6 + 0] = b4.x;
            out[rank * 6 + 1] = b4.y;
            out[rank * 6 + 2] = b4.z;
            out[rank * 6 + 3] = b4.w;
            out[rank * 6 + 4] = (float)g_cls[r];
            out[rank * 6 + 5] = __uint_as_float((unsigned)(key >> 32));
        }
    }

    // Reset counters for the next (graph-replayed) launch.
    __syncthreads();
    if (tid < NCLS) g_clsCnt[tid] = 0;
    if (tid == 128) g_bar1 = 0;
    if (tid == 129) g_bar2 = 0;
}

extern "C" void kernel_launch(void* const* d_in, const int* in_sizes, int n_in,
                              void* d_out, int out_size)
{
    const float* rois   = (const float*)d_in[0];
    const float* probs  = (const float*)d_in[1];
    const float* deltas = (const float*)d_in[2];
    const float* window = (const float*)d_in[3];
    float* out = (float*)d_out;

    k_all<<<GRID, TPB>>>(rois, probs, deltas, window, out);
}

// round 9
// speedup vs baseline: 1.7532x; 1.1518x over previous
#include <cuda_runtime.h>
#include <cstdint>

#define NBOX      5000
#define NCLS      81
#define MAXI      100
#define CLSMAX    128
#define GRID      125          // <= 148 SMs -> all co-resident (spin-safe)
#define TPB       320          // 10 warps: 1250 warps total = NBOX/4
#define NMSBLK    10           // blocks 0..9: 8 class-warps each = 80 classes
#define CANDCAP   512
#define MIN_CONF  0.7f
#define NMS_THR   0.3f

typedef unsigned long long ull;

// Persistent scratch. Counters zero at load; re-zeroed each launch by the
// last NMS block -> deterministic across graph replays.
__device__ ull    g_clsKeys[NCLS * CLSMAX];
__device__ float4 g_clsBox[NCLS * CLSMAX];
__device__ int    g_clsCnt[NCLS];
__device__ ull    g_keptKey[80 * MAXI];
__device__ float4 g_keptBox[80 * MAXI];
__device__ int    g_keptCnt[80];
__device__ int    g_hist[1024];
__device__ int    g_bar1;
__device__ int    g_bar2;

__device__ __forceinline__ int score_bin(float s) {
    int b = (int)((s - MIN_CONF) * (1024.0f / 0.3f));
    return min(1023, max(0, b));
}

struct P2 {                                    // phase-2 per-block workspace
    ull    keys[8][CLSMAX];                    // unsorted keys
    ull    skey[8][CLSMAX];                    // sorted keys
    float4 box[8][CLSMAX];                     // sorted boxes
    float  ar[8][CLSMAX];                      // sorted areas
    ull    m0[8][CLSMAX], m1[8][CLSMAX];       // overlap bit-matrix
};
struct P3 {                                    // phase-3 workspace
    int    hist[1024];
    ull    ckey[CANDCAP];
    float4 cbox[CANDCAP];
    int    ccls[CANDCAP];
    int    kcnt[80];
};
union SmemU { P2 p2; P3 p3; };

__global__ void __launch_bounds__(TPB)
k_all(const float* __restrict__ rois,
      const float* __restrict__ probs,
      const float* __restrict__ deltas,
      const float* __restrict__ window,
      float* __restrict__ out)
{
    const int tid  = threadIdx.x;
    const int warp = tid >> 5;
    const int lane = tid & 31;
    const int gw   = blockIdx.x * (TPB / 32) + warp;   // 0..1249

    __shared__ SmemU u;
    __shared__ int s_flag, s_ccnt, s_bstar;

    // ============ Phase 1: refine — exactly 4 ROIs per warp ================
    {
        const int r0 = 4 * gw;                         // rows r0..r0+3
        const float4 w4 = ((const float4*)window)[0];  // (wy1,wx1,wy2,wx2)

        float4 roi;
        if (lane < 4) roi = ((const float4*)rois)[r0 + lane];

        // All 12 probs loads issued upfront (independent -> high MLP).
        ull key[4];
        #pragma unroll
        for (int q = 0; q < 4; q++) {
            const float* p = probs + (size_t)(r0 + q) * NCLS;
            float v0 = p[lane];
            float v1 = p[lane + 32];
            float v2 = (lane < NCLS - 64) ? p[lane + 64] : -1.0f;
            ull k0 = ((ull)__float_as_uint(v0) << 32) | (0xFFFFFFFFu - (unsigned)lane);
            ull k1 = ((ull)__float_as_uint(v1) << 32) | (0xFFFFFFFFu - (unsigned)(lane + 32));
            ull k2 = (lane < NCLS - 64)
                   ? (((ull)__float_as_uint(v2) << 32) | (0xFFFFFFFFu - (unsigned)(lane + 64)))
                   : 0ULL;
            key[q] = max(k0, max(k1, k2));     // max prob, tie -> lower class
        }
        #pragma unroll
        for (int off = 16; off; off >>= 1) {
            #pragma unroll
            for (int q = 0; q < 4; q++) {
                ull o = __shfl_xor_sync(0xffffffffu, key[q], off);
                key[q] = max(key[q], o);
            }
        }

        if (lane < 4) {
            ull  k  = key[lane];
            float bp = __uint_as_float((unsigned)(k >> 32));
            int   bi = (int)(0xFFFFFFFFu - (unsigned)(k & 0xFFFFFFFFu));
            if (bi > 0 && bp >= MIN_CONF) {
                int r = r0 + lane;
                float4 d4 = *(const float4*)(deltas + ((size_t)r * NCLS + bi) * 4);
                float h  = roi.z - roi.x;
                float wd = roi.w - roi.y;
                float cy = roi.x + 0.5f * h;
                float cx = roi.y + 0.5f * wd;
                cy += (d4.x * 0.1f) * h;
                cx += (d4.y * 0.1f) * wd;
                h  *= expf(d4.z * 0.2f);
                wd *= expf(d4.w * 0.2f);
                float y1 = cy - 0.5f * h;
                float x1 = cx - 0.5f * wd;
                float y2 = y1 + h;
                float x2 = x1 + wd;
                y1 = fminf(fmaxf(y1, w4.x), w4.z);
                x1 = fminf(fmaxf(x1, w4.y), w4.w);
                y2 = fminf(fmaxf(y2, w4.x), w4.z);
                x2 = fminf(fmaxf(x2, w4.y), w4.w);

                ull okey = ((ull)__float_as_uint(bp) << 32) |
                           (unsigned)(0xFFFFFFFFu - (unsigned)r);
                int pos = atomicAdd(&g_clsCnt[bi], 1);
                if (pos < CLSMAX) {
                    g_clsKeys[bi * CLSMAX + pos] = okey;
                    g_clsBox[bi * CLSMAX + pos]  = make_float4(y1, x1, y2, x2);
                }
            }
        }
    }

    // ---- global barrier 1 (arrive; only NMS blocks wait) ----
    __syncthreads();
    if (tid == 0) {
        __threadfence();
        atomicAdd(&g_bar1, 1);
    }
    if (blockIdx.x >= NMSBLK) return;
    if (tid == 0) {
        while (*((volatile int*)&g_bar1) < GRID) { }
    }
    __syncthreads();
    __threadfence();

    // ============ Phase 2: NMS (blocks 0..9, warps 0..7 = classes) =========
    if (warp < 8) {
        const int cseg = blockIdx.x * 8 + warp;    // 0..79
        const int c    = cseg + 1;                 // class 1..80
        int cnt = min(g_clsCnt[c], CLSMAX);

        if (cnt > 0) {
            // Coalesced load of keys + boxes; keep local copies in registers.
            ull    lk[4];
            float4 lb[4];
            int    ln = 0;
            for (int t = lane; t < cnt; t += 32) {
                ull    kk = g_clsKeys[c * CLSMAX + t];
                float4 bb = g_clsBox[c * CLSMAX + t];
                u.p2.keys[warp][t] = kk;
                lk[ln] = kk; lb[ln] = bb; ln++;
            }
            __syncwarp();

            // Rank-sort (descending): rank = #{keys greater}; keys unique.
            {
                int t = lane;
                for (int s = 0; s < ln; s++, t += 32) {
                    ull k = lk[s];
                    int rk = 0;
                    for (int j = 0; j < cnt; j++) rk += (u.p2.keys[warp][j] > k);
                    float4 b = lb[s];
                    u.p2.skey[warp][rk] = k;
                    u.p2.box[warp][rk]  = b;
                    u.p2.ar[warp][rk]   = fmaxf(b.z - b.x, 0.0f) * fmaxf(b.w - b.y, 0.0f);
                }
            }
            __syncwarp();

            // Overlap bit-matrix; rows paired (p, cnt-1-p) for balance.
            int half = (cnt + 1) >> 1;
            for (int p = lane; p < half; p += 32) {
                #pragma unroll
                for (int side = 0; side < 2; side++) {
                    int i = side ? (cnt - 1 - p) : p;
                    if (side && i == p) break;
                    float4 bi = u.p2.box[warp][i];
                    float  ia = u.p2.ar[warp][i];
                    ull m0 = 0ULL, m1 = 0ULL;
                    for (int j = 0; j < i; j++) {
                        float4 bj = u.p2.box[warp][j];
                        float yy1 = fmaxf(bi.x, bj.x);
                        float xx1 = fmaxf(bi.y, bj.y);
                        float yy2 = fminf(bi.z, bj.z);
                        float xx2 = fminf(bi.w, bj.w);
                        float inter = fmaxf(yy2 - yy1, 0.0f) * fmaxf(xx2 - xx1, 0.0f);
                        float uni   = ia + u.p2.ar[warp][j] - inter;
                        // iou > THR  <=>  uni>0 && inter > THR*max(uni,1e-12)
                        if (uni > 0.0f && inter > NMS_THR * fmaxf(uni, 1e-12f)) {
                            if (j < 64) m0 |= 1ULL << j;
                            else        m1 |= 1ULL << (j - 64);
                        }
                    }
                    u.p2.m0[warp][i] = m0;
                    u.p2.m1[warp][i] = m1;
                }
            }
            __syncwarp();

            // Serial greedy sweep (replicated per lane; prefetched, pure ALU).
            ull kept0 = 0ULL, kept1 = 0ULL;
            int cntK = 0;
            ull nm0 = u.p2.m0[warp][0], nm1 = u.p2.m1[warp][0];
            for (int i = 0; i < cnt; i++) {
                ull m0 = nm0, m1 = nm1;
                if (i + 1 < cnt) { nm0 = u.p2.m0[warp][i + 1]; nm1 = u.p2.m1[warp][i + 1]; }
                bool ok = (((m0 & kept0) | (m1 & kept1)) == 0ULL) && (cntK < MAXI);
                if (ok) {
                    if (i < 64) kept0 |= 1ULL << i;
                    else        kept1 |= 1ULL << (i - 64);
                    cntK++;
                }
            }

            // Emit kept (key, box) in rank order + fire-and-forget histogram.
            for (int t = lane; t < cnt; t += 32) {
                bool isKept = (t < 64) ? ((kept0 >> t) & 1ULL)
                                       : ((kept1 >> (t - 64)) & 1ULL);
                if (isKept) {
                    int rank;
                    if (t < 64) rank = __popcll(kept0 & ((1ULL << t) - 1ULL));
                    else        rank = __popcll(kept0) +
                                       __popcll(kept1 & ((1ULL << (t - 64)) - 1ULL));
                    ull key = u.p2.skey[warp][t];
                    g_keptKey[cseg * MAXI + rank] = key;
                    g_keptBox[cseg * MAXI + rank] = u.p2.box[warp][t];
                    float sc = __uint_as_float((unsigned)(key >> 32));
                    atomicAdd(&g_hist[score_bin(sc)], 1);
                }
            }
            if (lane == 0) g_keptCnt[cseg] = cntK;
        } else {
            if (lane == 0) g_keptCnt[cseg] = 0;
        }
    }

    // ---- barrier 2: last-arriving NMS block runs phase 3 (no spin) ----
    __syncthreads();
    if (tid == 0) {
        __threadfence();
        int prev = atomicAdd(&g_bar2, 1);
        s_flag = (prev == NMSBLK - 1);
    }
    __syncthreads();
    if (!s_flag) return;
    __threadfence();

    // ==================== Phase 3: top-100 (last block) =====================
    for (int b = tid; b < 1024; b += TPB) {
        u.p3.hist[b] = g_hist[b];
        g_hist[b] = 0;                         // clear for next launch
    }
    if (tid < 80) u.p3.kcnt[tid] = g_keptCnt[tid];
    if (tid == 0) { s_ccnt = 0; s_bstar = 0; }
    if (tid < MAXI) {
        #pragma unroll
        for (int q = 0; q < 6; q++) out[tid * 6 + q] = 0.0f;
    }
    __syncthreads();

    // Warp 0: suffix-scan 1024 bins; B = largest bin with S(B) >= MAXI.
    if (warp == 0) {
        int base = lane * 32;
        int csum = 0;
        #pragma unroll
        for (int b = 0; b < 32; b++) csum += u.p3.hist[base + b];
        int v = csum;
        #pragma unroll
        for (int off = 1; off < 32; off <<= 1) {
            int t = __shfl_down_sync(0xffffffffu, v, off);
            if (lane + off < 32) v += t;
        }
        int running = v - csum;                // suffix of higher 32-chunks
        for (int b = 31; b >= 0; b--) {
            int S = running + u.p3.hist[base + b];
            if (S >= MAXI && running < MAXI) s_bstar = base + b;
            running = S;
        }
    }
    __syncthreads();
    const int B = s_bstar;

    // Collect candidates with bin >= B (key + box + class; no gathers later).
    for (int s = tid; s < 80 * MAXI; s += TPB) {
        int seg = s / MAXI, k = s - seg * MAXI;
        if (k < u.p3.kcnt[seg]) {
            ull key = g_keptKey[s];
            float sc = __uint_as_float((unsigned)(key >> 32));
            if (score_bin(sc) >= B) {
                int pos = atomicAdd(&s_ccnt, 1);
                if (pos < CANDCAP) {
                    u.p3.ckey[pos] = key;
                    u.p3.cbox[pos] = g_keptBox[s];
                    u.p3.ccls[pos] = seg + 1;
                }
            }
        }
    }
    __syncthreads();
    int k2 = min(s_ccnt, CANDCAP);

    // Rank-select: rank = #{keys greater}; unique keys -> unique ranks.
    for (int t = tid; t < k2; t += TPB) {
        ull key = u.p3.ckey[t];
        int rank = 0;
        for (int j = 0; j < k2; j++) rank += (u.p3.ckey[j] > key);
        if (rank < MAXI) {
            float4 b4 = u.p3.cbox[t];
            out[rank * 6 + 0] = b4.x;
            out[rank * 6 + 1] = b4.y;
            out[rank * 6 + 2] = b4.z;
            out[rank * 6 + 3] = b4.w;
            out[rank * 6 + 4] = (float)u.p3.ccls[t];
            out[rank * 6 + 5] = __uint_as_float((unsigned)(key >> 32));
        }
    }

    // Reset counters for the next (graph-replayed) launch.
    __syncthreads();
    if (tid < NCLS) g_clsCnt[tid] = 0;
    if (tid == 128) g_bar1 = 0;
    if (tid == 129) g_bar2 = 0;
}

extern "C" void kernel_launch(void* const* d_in, const int* in_sizes, int n_in,
                              void* d_out, int out_size)
{
    const float* rois   = (const float*)d_in[0];
    const float* probs  = (const float*)d_in[1];
    const float* deltas = (const float*)d_in[2];
    const float* window = (const float*)d_in[3];
    float* out = (float*)d_out;

    k_all<<<GRID, TPB>>>(rois, probs, deltas, window, out);
}

// round 11
// speedup vs baseline: 2.3684x; 1.3509x over previous
#include <cuda_runtime.h>
#include <cstdint>

#define NBOX      5000
#define NCLS      81
#define MAXI      100
#define CLSMAX    128
#define GRID      125          // <= 148 SMs -> all co-resident (spin-safe)
#define TPB       320          // 10 warps: 1250 warps total = NBOX/4
#define NMSBLK    80           // blocks 0..79: one block per class
#define CANDCAP   512
#define MIN_CONF  0.7f
#define NMS_THR   0.3f

typedef unsigned long long ull;

// Persistent scratch. Counters zero at load; re-zeroed each launch by the
// phase-3 block -> deterministic across graph replays.
__device__ ull    g_clsKeys[NCLS * CLSMAX];
__device__ float4 g_clsBox[NCLS * CLSMAX];
__device__ int    g_clsCnt[NCLS];
__device__ ull    g_keptKey[80 * MAXI];
__device__ float4 g_keptBox[80 * MAXI];
__device__ int    g_keptCnt[80];
__device__ int    g_hist[1024];
__device__ int    g_bar1;
__device__ int    g_bar2;

__device__ __forceinline__ int score_bin(float s) {
    int b = (int)((s - MIN_CONF) * (1024.0f / 0.3f));
    return min(1023, max(0, b));
}

struct P2 {                        // phase-2 workspace: ONE class per block
    ull    keys[CLSMAX];           // unsorted keys
    ull    skey[CLSMAX];           // sorted keys
    float4 box[CLSMAX];            // sorted boxes
    float  ar[CLSMAX];             // sorted areas
    uint4  mask[CLSMAX];           // 128-bit overlap mask per row (word k = j in [32k,32k+32))
};
struct P3 {                        // phase-3 workspace
    int    hist[1024];
    ull    ckey[CANDCAP];
    float4 cbox[CANDCAP];
    int    ccls[CANDCAP];
    int    kcnt[80];
};
union SmemU { P2 p2; P3 p3; };

__global__ void __launch_bounds__(TPB)
k_all(const float* __restrict__ rois,
      const float* __restrict__ probs,
      const float* __restrict__ deltas,
      const float* __restrict__ window,
      float* __restrict__ out)
{
    const int tid  = threadIdx.x;
    const int warp = tid >> 5;
    const int lane = tid & 31;
    const int gw   = blockIdx.x * (TPB / 32) + warp;   // 0..1249

    __shared__ SmemU u;
    __shared__ int s_flag, s_ccnt, s_bstar;

    // ============ Phase 1: refine — exactly 4 ROIs per warp ================
    {
        const int r0 = 4 * gw;                         // rows r0..r0+3
        const float4 w4 = ((const float4*)window)[0];  // (wy1,wx1,wy2,wx2)

        float4 roi;
        if (lane < 4) roi = ((const float4*)rois)[r0 + lane];

        // All 12 probs loads issued upfront (independent -> high MLP).
        ull key[4];
        #pragma unroll
        for (int q = 0; q < 4; q++) {
            const float* p = probs + (size_t)(r0 + q) * NCLS;
            float v0 = p[lane];
            float v1 = p[lane + 32];
            float v2 = (lane < NCLS - 64) ? p[lane + 64] : -1.0f;
            ull k0 = ((ull)__float_as_uint(v0) << 32) | (0xFFFFFFFFu - (unsigned)lane);
            ull k1 = ((ull)__float_as_uint(v1) << 32) | (0xFFFFFFFFu - (unsigned)(lane + 32));
            ull k2 = (lane < NCLS - 64)
                   ? (((ull)__float_as_uint(v2) << 32) | (0xFFFFFFFFu - (unsigned)(lane + 64)))
                   : 0ULL;
            key[q] = max(k0, max(k1, k2));     // max prob, tie -> lower class
        }
        #pragma unroll
        for (int off = 16; off; off >>= 1) {
            #pragma unroll
            for (int q = 0; q < 4; q++) {
                ull o = __shfl_xor_sync(0xffffffffu, key[q], off);
                key[q] = max(key[q], o);
            }
        }

        if (lane < 4) {
            ull  k  = key[lane];
            float bp = __uint_as_float((unsigned)(k >> 32));
            int   bi = (int)(0xFFFFFFFFu - (unsigned)(k & 0xFFFFFFFFu));
            if (bi > 0 && bp >= MIN_CONF) {
                int r = r0 + lane;
                float4 d4 = *(const float4*)(deltas + ((size_t)r * NCLS + bi) * 4);
                float h  = roi.z - roi.x;
                float wd = roi.w - roi.y;
                float cy = roi.x + 0.5f * h;
                float cx = roi.y + 0.5f * wd;
                cy += (d4.x * 0.1f) * h;
                cx += (d4.y * 0.1f) * wd;
                h  *= expf(d4.z * 0.2f);
                wd *= expf(d4.w * 0.2f);
                float y1 = cy - 0.5f * h;
                float x1 = cx - 0.5f * wd;
                float y2 = y1 + h;
                float x2 = x1 + wd;
                y1 = fminf(fmaxf(y1, w4.x), w4.z);
                x1 = fminf(fmaxf(x1, w4.y), w4.w);
                y2 = fminf(fmaxf(y2, w4.x), w4.z);
                x2 = fminf(fmaxf(x2, w4.y), w4.w);

                ull okey = ((ull)__float_as_uint(bp) << 32) |
                           (unsigned)(0xFFFFFFFFu - (unsigned)r);
                int pos = atomicAdd(&g_clsCnt[bi], 1);
                if (pos < CLSMAX) {
                    g_clsKeys[bi * CLSMAX + pos] = okey;
                    g_clsBox[bi * CLSMAX + pos]  = make_float4(y1, x1, y2, x2);
                }
            }
        }
    }

    // ---- global barrier 1 (arrive; only NMS blocks wait) ----
    __syncthreads();
    if (tid == 0) {
        __threadfence();
        atomicAdd(&g_bar1, 1);
    }
    if (blockIdx.x >= NMSBLK) return;
    if (tid == 0) {
        while (*((volatile int*)&g_bar1) < GRID) { }
    }
    __syncthreads();
    __threadfence();

    // ============ Phase 2: NMS — one block per class ========================
    const int cseg = blockIdx.x;           // 0..79
    const int c    = cseg + 1;             // class 1..80
    int cnt = min(g_clsCnt[c], CLSMAX);

    if (cnt > 0) {
        // Load keys (coalesced) into shared.
        ull    myKey = 0;
        float4 myBox;
        if (tid < cnt) {
            myKey = g_clsKeys[c * CLSMAX + tid];
            myBox = g_clsBox[c * CLSMAX + tid];
            u.p2.keys[tid] = myKey;
        }
        __syncthreads();

        // Block rank-sort (descending): rank = #{keys greater}; keys unique.
        if (tid < cnt) {
            int rk = 0;
            for (int j = 0; j < cnt; j++) rk += (u.p2.keys[j] > myKey);
            u.p2.skey[rk] = myKey;
            u.p2.box[rk]  = myBox;
            u.p2.ar[rk]   = fmaxf(myBox.z - myBox.x, 0.0f) *
                            fmaxf(myBox.w - myBox.y, 0.0f);
        }
        __syncthreads();

        // Overlap mask build: work item = (row i, 32-wide j-chunk k).
        // Each item computes one 32-bit word; <=32 IoU evals per item.
        for (int item = tid; item < cnt * 4; item += TPB) {
            int i = item & (CLSMAX - 1);           // cnt<=128: item % 128? no -
            i = item % cnt;
            int k = item / cnt;                    // 0..3
            float4 bi = u.p2.box[i];
            float  ia = u.p2.ar[i];
            unsigned w = 0u;
            int jend = min(i, (k + 1) * 32);
            for (int j = k * 32; j < jend; j++) {
                float4 bj = u.p2.box[j];
                float yy1 = fmaxf(bi.x, bj.x);
                float xx1 = fmaxf(bi.y, bj.y);
                float yy2 = fminf(bi.z, bj.z);
                float xx2 = fminf(bi.w, bj.w);
                float inter = fmaxf(yy2 - yy1, 0.0f) * fmaxf(xx2 - xx1, 0.0f);
                float uni   = ia + u.p2.ar[j] - inter;
                // iou > THR  <=>  uni>0 && inter > THR*max(uni,1e-12)
                if (uni > 0.0f && inter > NMS_THR * fmaxf(uni, 1e-12f))
                    w |= 1u << (j - k * 32);
            }
            ((unsigned*)&u.p2.mask[i])[k] = w;
        }
        __syncthreads();

        // Serial greedy sweep, replicated in every thread (broadcast LDS.128,
        // prefetched, pure ALU).
        ull kept0 = 0ULL, kept1 = 0ULL;
        int cntK = 0;
        uint4 nxt = u.p2.mask[0];
        for (int i = 0; i < cnt; i++) {
            uint4 cur = nxt;
            if (i + 1 < cnt) nxt = u.p2.mask[i + 1];
            ull lo = (ull)cur.x | ((ull)cur.y << 32);
            ull hi = (ull)cur.z | ((ull)cur.w << 32);
            bool ok = (((lo & kept0) | (hi & kept1)) == 0ULL) && (cntK < MAXI);
            if (ok) {
                if (i < 64) kept0 |= 1ULL << i;
                else        kept1 |= 1ULL << (i - 64);
                cntK++;
            }
        }

        // Emit kept (key, box) in rank order + fire-and-forget histogram.
        if (tid < cnt) {
            int t = tid;
            bool isKept = (t < 64) ? ((kept0 >> t) & 1ULL)
                                   : ((kept1 >> (t - 64)) & 1ULL);
            if (isKept) {
                int rank;
                if (t < 64) rank = __popcll(kept0 & ((1ULL << t) - 1ULL));
                else        rank = __popcll(kept0) +
                                   __popcll(kept1 & ((1ULL << (t - 64)) - 1ULL));
                ull key = u.p2.skey[t];
                g_keptKey[cseg * MAXI + rank] = key;
                g_keptBox[cseg * MAXI + rank] = u.p2.box[t];
                float sc = __uint_as_float((unsigned)(key >> 32));
                atomicAdd(&g_hist[score_bin(sc)], 1);
            }
        }
        if (tid == 0) g_keptCnt[cseg] = cntK;
    } else {
        if (tid == 0) g_keptCnt[cseg] = 0;
    }

    // ---- barrier 2: last-arriving NMS block runs phase 3 (no spin) ----
    __syncthreads();
    if (tid == 0) {
        __threadfence();
        int prev = atomicAdd(&g_bar2, 1);
        s_flag = (prev == NMSBLK - 1);
    }
    __syncthreads();
    if (!s_flag) return;
    __threadfence();

    // ==================== Phase 3: top-100 (last block) =====================
    for (int b = tid; b < 1024; b += TPB) {
        u.p3.hist[b] = g_hist[b];
        g_hist[b] = 0;                         // clear for next launch
    }
    if (tid < 80) u.p3.kcnt[tid] = g_keptCnt[tid];
    if (tid == 0) { s_ccnt = 0; s_bstar = 0; }
    if (tid < MAXI) {
        #pragma unroll
        for (int q = 0; q < 6; q++) out[tid * 6 + q] = 0.0f;
    }
    __syncthreads();

    // Warp 0: suffix-scan 1024 bins; B = largest bin with S(B) >= MAXI.
    if (warp == 0) {
        int base = lane * 32;
        int csum = 0;
        #pragma unroll
        for (int b = 0; b < 32; b++) csum += u.p3.hist[base + b];
        int v = csum;
        #pragma unroll
        for (int off = 1; off < 32; off <<= 1) {
            int t = __shfl_down_sync(0xffffffffu, v, off);
            if (lane + off < 32) v += t;
        }
        int running = v - csum;                // suffix of higher 32-chunks
        for (int b = 31; b >= 0; b--) {
            int S = running + u.p3.hist[base + b];
            if (S >= MAXI && running < MAXI) s_bstar = base + b;
            running = S;
        }
    }
    __syncthreads();
    const int B = s_bstar;

    // Collect candidates with bin >= B (key + box + class; no gathers later).
    for (int s = tid; s < 80 * MAXI; s += TPB) {
        int seg = s / MAXI, k = s - seg * MAXI;
        if (k < u.p3.kcnt[seg]) {
            ull key = g_keptKey[s];
            float sc = __uint_as_float((unsigned)(key >> 32));
            if (score_bin(sc) >= B) {
                int pos = atomicAdd(&s_ccnt, 1);
                if (pos < CANDCAP) {
                    u.p3.ckey[pos] = key;
                    u.p3.cbox[pos] = g_keptBox[s];
                    u.p3.ccls[pos] = seg + 1;
                }
            }
        }
    }
    __syncthreads();
    int k2 = min(s_ccnt, CANDCAP);

    // Rank-select: rank = #{keys greater}; unique keys -> unique ranks.
    for (int t = tid; t < k2; t += TPB) {
        ull key = u.p3.ckey[t];
        int rank = 0;
        for (int j = 0; j < k2; j++) rank += (u.p3.ckey[j] > key);
        if (rank < MAXI) {
            float4 b4 = u.p3.cbox[t];
            out[rank * 6 + 0] = b4.x;
            out[rank * 6 + 1] = b4.y;
            out[rank * 6 + 2] = b4.z;
            out[rank * 6 + 3] = b4.w;
            out[rank * 6 + 4] = (float)u.p3.ccls[t];
            out[rank * 6 + 5] = __uint_as_float((unsigned)(key >> 32));
        }
    }

    // Reset counters for the next (graph-replayed) launch.
    __syncthreads();
    if (tid < NCLS) g_clsCnt[tid] = 0;
    if (tid == 128) g_bar1 = 0;
    if (tid == 129) g_bar2 = 0;
}

extern "C" void kernel_launch(void* const* d_in, const int* in_sizes, int n_in,
                              void* d_out, int out_size)
{
    const float* rois   = (const float*)d_in[0];
    const float* probs  = (const float*)d_in[1];
    const float* deltas = (const float*)d_in[2];
    const float* window = (const float*)d_in[3];
    float* out = (float*)d_out;

    k_all<<<GRID, TPB>>>(rois, probs, deltas, window, out);
}

// round 12
// speedup vs baseline: 2.9428x; 1.2425x over previous
#include <cuda_runtime.h>
#include <cstdint>

#define NBOX      5000
#define NCLS      81
#define MAXI      100
#define CLSMAX    128
#define GRID      80           // one block per class; all co-resident
#define TPB       512          // 16 warps -> 1280 warps >= 1250 ROI-quads
#define KEPTMAX   (80 * MAXI)
#define CANDCAP   512
#define MIN_CONF  0.7f
#define NMS_THR   0.3f

typedef unsigned long long ull;

// Persistent scratch. Counters zero at load; re-zeroed each launch by the
// phase-3 block -> deterministic across graph replays.
__device__ ull    g_clsKeys[NCLS * CLSMAX];
__device__ float4 g_clsBox[NCLS * CLSMAX];
__device__ int    g_clsCnt[NCLS];
__device__ ull    g_kKey[KEPTMAX];          // compact kept list
__device__ float4 g_kBox[KEPTMAX];
__device__ int    g_kCls[KEPTMAX];
__device__ int    g_keptTotal;
__device__ int    g_hist[1024];
__device__ int    g_bar1;
__device__ int    g_bar2;

__device__ __forceinline__ int score_bin(float s) {
    int b = (int)((s - MIN_CONF) * (1024.0f / 0.3f));
    return min(1023, max(0, b));
}

struct P2 {                        // phase-2 workspace: ONE class per block
    ull    keys[CLSMAX];
    ull    skey[CLSMAX];
    float4 box[CLSMAX];
    float  ar[CLSMAX];
    uint4  mask[CLSMAX];           // 128-bit overlap mask per row
};
struct P3 {                        // phase-3 workspace
    int    hist[1024];
    ull    ckey[CANDCAP];
    float4 cbox[CANDCAP];
    int    ccls[CANDCAP];
};
union SmemU { P2 p2; P3 p3; };

__global__ void __launch_bounds__(TPB)
k_all(const float* __restrict__ rois,
      const float* __restrict__ probs,
      const float* __restrict__ deltas,
      const float* __restrict__ window,
      float* __restrict__ out)
{
    const int tid  = threadIdx.x;
    const int warp = tid >> 5;
    const int lane = tid & 31;
    const int gw   = blockIdx.x * (TPB / 32) + warp;   // 0..1279

    __shared__ SmemU u;
    __shared__ int s_flag, s_ccnt, s_bstar, s_base;

    // ============ Phase 1: refine — one ROI-quad per warp ==================
    const int r0 = 4 * gw;
    if (r0 < NBOX) {
        const float4 w4 = ((const float4*)window)[0];  // (wy1,wx1,wy2,wx2)

        float4 roi;
        if (lane < 4) roi = ((const float4*)rois)[r0 + lane];

        // All 12 probs loads issued upfront (independent -> high MLP).
        ull key[4];
        #pragma unroll
        for (int q = 0; q < 4; q++) {
            const float* p = probs + (size_t)(r0 + q) * NCLS;
            float v0 = p[lane];
            float v1 = p[lane + 32];
            float v2 = (lane < NCLS - 64) ? p[lane + 64] : -1.0f;
            ull k0 = ((ull)__float_as_uint(v0) << 32) | (0xFFFFFFFFu - (unsigned)lane);
            ull k1 = ((ull)__float_as_uint(v1) << 32) | (0xFFFFFFFFu - (unsigned)(lane + 32));
            ull k2 = (lane < NCLS - 64)
                   ? (((ull)__float_as_uint(v2) << 32) | (0xFFFFFFFFu - (unsigned)(lane + 64)))
                   : 0ULL;
            key[q] = max(k0, max(k1, k2));     // max prob, tie -> lower class
        }
        #pragma unroll
        for (int off = 16; off; off >>= 1) {
            #pragma unroll
            for (int q = 0; q < 4; q++) {
                ull o = __shfl_xor_sync(0xffffffffu, key[q], off);
                key[q] = max(key[q], o);
            }
        }

        if (lane < 4) {
            ull  k  = key[lane];
            float bp = __uint_as_float((unsigned)(k >> 32));
            int   bi = (int)(0xFFFFFFFFu - (unsigned)(k & 0xFFFFFFFFu));
            if (bi > 0 && bp >= MIN_CONF) {
                int r = r0 + lane;
                float4 d4 = *(const float4*)(deltas + ((size_t)r * NCLS + bi) * 4);
                float h  = roi.z - roi.x;
                float wd = roi.w - roi.y;
                float cy = roi.x + 0.5f * h;
                float cx = roi.y + 0.5f * wd;
                cy += (d4.x * 0.1f) * h;
                cx += (d4.y * 0.1f) * wd;
                h  *= expf(d4.z * 0.2f);
                wd *= expf(d4.w * 0.2f);
                float y1 = cy - 0.5f * h;
                float x1 = cx - 0.5f * wd;
                float y2 = y1 + h;
                float x2 = x1 + wd;
                y1 = fminf(fmaxf(y1, w4.x), w4.z);
                x1 = fminf(fmaxf(x1, w4.y), w4.w);
                y2 = fminf(fmaxf(y2, w4.x), w4.z);
                x2 = fminf(fmaxf(x2, w4.y), w4.w);

                ull okey = ((ull)__float_as_uint(bp) << 32) |
                           (unsigned)(0xFFFFFFFFu - (unsigned)r);
                int pos = atomicAdd(&g_clsCnt[bi], 1);
                if (pos < CLSMAX) {
                    g_clsKeys[bi * CLSMAX + pos] = okey;
                    g_clsBox[bi * CLSMAX + pos]  = make_float4(y1, x1, y2, x2);
                }
            }
        }
    }

    // ---- global barrier 1: all 80 blocks arrive, all wait ----
    __syncthreads();
    if (tid == 0) {
        __threadfence();
        atomicAdd(&g_bar1, 1);
        while (*((volatile int*)&g_bar1) < GRID) { }
    }
    __syncthreads();
    __threadfence();

    // ============ Phase 2: NMS — one block per class ========================
    const int cseg = blockIdx.x;           // 0..79
    const int c    = cseg + 1;             // class 1..80
    int cnt = min(g_clsCnt[c], CLSMAX);
    int cntK = 0;
    ull kept0 = 0ULL, kept1 = 0ULL;

    if (cnt > 0) {
        ull    myKey = 0;
        float4 myBox;
        if (tid < cnt) {
            myKey = g_clsKeys[c * CLSMAX + tid];
            myBox = g_clsBox[c * CLSMAX + tid];
            u.p2.keys[tid] = myKey;
        }
        __syncthreads();

        // Block rank-sort (descending): rank = #{keys greater}; keys unique.
        if (tid < cnt) {
            int rk = 0;
            for (int j = 0; j < cnt; j++) rk += (u.p2.keys[j] > myKey);
            u.p2.skey[rk] = myKey;
            u.p2.box[rk]  = myBox;
            u.p2.ar[rk]   = fmaxf(myBox.z - myBox.x, 0.0f) *
                            fmaxf(myBox.w - myBox.y, 0.0f);
        }
        __syncthreads();

        // Overlap mask build: one (row i, 32-wide chunk k) item per thread.
        if (tid < cnt * 4) {
            int i = tid % cnt;
            int k = tid / cnt;                 // 0..3
            float4 bi = u.p2.box[i];
            float  ia = u.p2.ar[i];
            unsigned w = 0u;
            int jend = min(i, (k + 1) * 32);
            for (int j = k * 32; j < jend; j++) {
                float4 bj = u.p2.box[j];
                float yy1 = fmaxf(bi.x, bj.x);
                float xx1 = fmaxf(bi.y, bj.y);
                float yy2 = fminf(bi.z, bj.z);
                float xx2 = fminf(bi.w, bj.w);
                float inter = fmaxf(yy2 - yy1, 0.0f) * fmaxf(xx2 - xx1, 0.0f);
                float uni   = ia + u.p2.ar[j] - inter;
                // iou > THR  <=>  uni>0 && inter > THR*max(uni,1e-12)
                if (uni > 0.0f && inter > NMS_THR * fmaxf(uni, 1e-12f))
                    w |= 1u << (j - k * 32);
            }
            ((unsigned*)&u.p2.mask[i])[k] = w;
        }
        __syncthreads();

        // Serial greedy sweep, replicated per thread (broadcast LDS.128,
        // prefetched, pure ALU).
        uint4 nxt = u.p2.mask[0];
        for (int i = 0; i < cnt; i++) {
            uint4 cur = nxt;
            if (i + 1 < cnt) nxt = u.p2.mask[i + 1];
            ull lo = (ull)cur.x | ((ull)cur.y << 32);
            ull hi = (ull)cur.z | ((ull)cur.w << 32);
            bool ok = (((lo & kept0) | (hi & kept1)) == 0ULL) && (cntK < MAXI);
            if (ok) {
                if (i < 64) kept0 |= 1ULL << i;
                else        kept1 |= 1ULL << (i - 64);
                cntK++;
            }
        }

        // Reserve a compact segment, then emit kept (key, box, cls) + hist.
        if (tid == 0) s_base = atomicAdd(&g_keptTotal, cntK);
        __syncthreads();
        int base = s_base;

        if (tid < cnt) {
            int t = tid;
            bool isKept = (t < 64) ? ((kept0 >> t) & 1ULL)
                                   : ((kept1 >> (t - 64)) & 1ULL);
            if (isKept) {
                int rank;
                if (t < 64) rank = __popcll(kept0 & ((1ULL << t) - 1ULL));
                else        rank = __popcll(kept0) +
                                   __popcll(kept1 & ((1ULL << (t - 64)) - 1ULL));
                ull key = u.p2.skey[t];
                g_kKey[base + rank] = key;
                g_kBox[base + rank] = u.p2.box[t];
                g_kCls[base + rank] = c;
                float sc = __uint_as_float((unsigned)(key >> 32));
                atomicAdd(&g_hist[score_bin(sc)], 1);
            }
        }
    }

    // ---- barrier 2: last-arriving block runs phase 3 (no spin) ----
    __syncthreads();
    if (tid == 0) {
        __threadfence();
        int prev = atomicAdd(&g_bar2, 1);
        s_flag = (prev == GRID - 1);
    }
    __syncthreads();
    if (!s_flag) return;
    __threadfence();

    // ==================== Phase 3: top-100 (last block) =====================
    const int n = *((volatile int*)&g_keptTotal);

    for (int b = tid; b < 1024; b += TPB) {
        u.p3.hist[b] = g_hist[b];
        g_hist[b] = 0;                         // clear for next launch
    }
    if (tid == 0) { s_ccnt = 0; s_bstar = 0; }
    if (tid < MAXI) {
        #pragma unroll
        for (int q = 0; q < 6; q++) out[tid * 6 + q] = 0.0f;
    }
    __syncthreads();

    // Warp 0: suffix-scan 1024 bins; B = largest bin with S(B) >= MAXI.
    if (warp == 0) {
        int base = lane * 32;
        int csum = 0;
        #pragma unroll
        for (int b = 0; b < 32; b++) csum += u.p3.hist[base + b];
        int v = csum;
        #pragma unroll
        for (int off = 1; off < 32; off <<= 1) {
            int t = __shfl_down_sync(0xffffffffu, v, off);
            if (lane + off < 32) v += t;
        }
        int running = v - csum;                // suffix of higher 32-chunks
        for (int b = 31; b >= 0; b--) {
            int S = running + u.p3.hist[base + b];
            if (S >= MAXI && running < MAXI) s_bstar = base + b;
            running = S;
        }
    }
    __syncthreads();
    const int B = s_bstar;

    // Collect candidates with bin >= B from the compact list (coalesced).
    for (int s = tid; s < n; s += TPB) {
        ull key = g_kKey[s];
        float sc = __uint_as_float((unsigned)(key >> 32));
        if (score_bin(sc) >= B) {
            int pos = atomicAdd(&s_ccnt, 1);
            if (pos < CANDCAP) {
                u.p3.ckey[pos] = key;
                u.p3.cbox[pos] = g_kBox[s];    // issued now, consumed post-sync
                u.p3.ccls[pos] = g_kCls[s];
            }
        }
    }
    __syncthreads();
    int k2 = min(s_ccnt, CANDCAP);

    // Rank-select: rank = #{keys greater}; unique keys -> unique ranks.
    for (int t = tid; t < k2; t += TPB) {
        ull key = u.p3.ckey[t];
        int rank = 0;
        for (int j = 0; j < k2; j++) rank += (u.p3.ckey[j] > key);
        if (rank < MAXI) {
            float4 b4 = u.p3.cbox[t];
            out[rank * 6 + 0] = b4.x;
            out[rank * 6 + 1] = b4.y;
            out[rank * 6 + 2] = b4.z;
            out[rank * 6 + 3] = b4.w;
            out[rank * 6 + 4] = (float)u.p3.ccls[t];
            out[rank * 6 + 5] = __uint_as_float((unsigned)(key >> 32));
        }
    }

    // Reset counters for the next (graph-replayed) launch.
    __syncthreads();
    if (tid < NCLS) g_clsCnt[tid] = 0;
    if (tid == 128) g_bar1 = 0;
    if (tid == 129) g_bar2 = 0;
    if (tid == 130) g_keptTotal = 0;
}

extern "C" void kernel_launch(void* const* d_in, const int* in_sizes, int n_in,
                              void* d_out, int out_size)
{
    const float* rois   = (const float*)d_in[0];
    const float* probs  = (const float*)d_in[1];
    const float* deltas = (const float*)d_in[2];
    const float* window = (const float*)d_in[3];
    float* out = (float*)d_out;

    k_all<<<GRID, TPB>>>(rois, probs, deltas, window, out);
}